// round 14
// baseline (speedup 1.0000x reference)
#include <cuda_runtime.h>
#include <cuda_bf16.h>
#include <math.h>

typedef unsigned long long ull;

#define Bb 32
#define Tt 64
#define Ss 64
#define Ee 256
#define Hh 512
#define Aa 512
#define DVv 32000

// ---------------- device scratch (no allocation allowed) ----------------
__device__ float g_encproj[Bb * Ss * Aa];        // 4 MB
__device__ float g_h0[2][Bb * Hh];
__device__ float g_h1[2][Bb * Hh];
__device__ float g_c0[Bb * Hh];
__device__ float g_c1[Bb * Hh];
__device__ float g_x0[Bb * (Hh + Ee)];
__device__ float g_Hall[Tt * Bb * Hh];           // 4 MB, h1 per step
// repacked LSTM weights: per block tile bx (32 cols = 8 units x 4 gates),
// full-K contiguous: [k2][np(16)][jp(2)] ull f32x2 col-pairs
__device__ ull g_wpk0[64 * 1280 * 16];           // 10.5 MB (K=1280)
__device__ ull g_wpk1[64 * 1024 * 16];           // 8.4 MB  (K=1024)
// logits tensor-core operands (bf16 2-term split)
__device__ __nv_bfloat16 g_HallHi[Tt * Bb * Hh]; // 2 MB
__device__ __nv_bfloat16 g_HallLo[Tt * Bb * Hh]; // 2 MB
__device__ __nv_bfloat16 g_WdtHi[(size_t)DVv * Hh]; // 32.8 MB, [n][k]
__device__ __nv_bfloat16 g_WdtLo[(size_t)DVv * Hh]; // 32.8 MB

// ---------------- packed fp32x2 helpers (Blackwell FFMA2) ----------------
__device__ __forceinline__ void ffma2(ull &c, ull a, ull b) {
    asm("fma.rn.f32x2 %0, %1, %2, %0;" : "+l"(c) : "l"(a), "l"(b));
}
__device__ __forceinline__ ull pack2(float x, float y) {
    ull r; asm("mov.b64 %0, {%1, %2};" : "=l"(r) : "f"(x), "f"(y)); return r;
}
__device__ __forceinline__ float2 unpack2(ull v) {
    float2 f; asm("mov.b64 {%0, %1}, %2;" : "=f"(f.x), "=f"(f.y) : "l"(v)); return f;
}
__device__ __forceinline__ float tanh_fast(float x) {
    float y; asm("tanh.approx.f32 %0, %1;" : "=f"(y) : "f"(x)); return y;
}
__device__ __forceinline__ unsigned smem_u32(const void* p) {
    unsigned a;
    asm("{ .reg .u64 t; cvta.to.shared.u64 t, %1; cvt.u32.u64 %0, t; }"
        : "=r"(a) : "l"(p));
    return a;
}

// ---------------- mma.sync helpers (arch-neutral tensor core path) ----------
__device__ __forceinline__ void ldsm4(unsigned* r, unsigned addr) {
    asm volatile("ldmatrix.sync.aligned.m8n8.x4.shared.b16 {%0,%1,%2,%3}, [%4];"
                 : "=r"(r[0]), "=r"(r[1]), "=r"(r[2]), "=r"(r[3]) : "r"(addr));
}
__device__ __forceinline__ void mma16816(float* d, const unsigned* a,
                                         const unsigned* b) {
    asm volatile(
        "mma.sync.aligned.m16n8k16.row.col.f32.bf16.bf16.f32 "
        "{%0,%1,%2,%3}, {%4,%5,%6,%7}, {%8,%9}, {%0,%1,%2,%3};"
        : "+f"(d[0]), "+f"(d[1]), "+f"(d[2]), "+f"(d[3])
        : "r"(a[0]), "r"(a[1]), "r"(a[2]), "r"(a[3]), "r"(b[0]), "r"(b[1]));
}

// ---------------- init / tail ----------------
__global__ void init_state(const float* __restrict__ hidden0,
                           const float* __restrict__ cell0) {
    int i = blockIdx.x * 256 + threadIdx.x;
    if (i < Bb * Hh) {
        g_h0[0][i] = hidden0[i];
        g_h1[0][i] = hidden0[Bb * Hh + i];
        g_c0[i]    = cell0[i];
        g_c1[i]    = cell0[Bb * Hh + i];
    }
}

__global__ void write_tail(float* __restrict__ out) {
    int i = blockIdx.x * 256 + threadIdx.x;
    const int fin = (Tt & 1);  // T=64 -> final h lives in buffer 0
    if (i < Bb * Hh) {
        out[i]               = g_h0[fin][i];
        out[Bb * Hh + i]     = g_h1[fin][i];
        out[2 * Bb * Hh + i] = g_c0[i];
        out[3 * Bb * Hh + i] = g_c1[i];
    }
}

// ---------------- weight repack: gate-interleaved full-K tiles ----------
// Tile bx: 32 cols, col c <-> unit u=c>>2 (j = bx*8+u), gate g=c&3
// (wcol = g*512 + j). dst ull i: tile = i/(KT*16); ti: k2=ti>>5,
// np=(ti&31)>>1, jp=ti&1; kg=2k2+jp; pair covers cols (2np, 2np+1).
template<int LAYER>
__global__ __launch_bounds__(256) void repack_w(const float* __restrict__ Wx,
                                                const float* __restrict__ Wh) {
    constexpr int KX = LAYER ? Hh : (Hh + Ee);
    constexpr int KT = KX + Hh;            // 1024 / 1280
    ull* dst = LAYER ? g_wpk1 : g_wpk0;
    int i = blockIdx.x * 256 + threadIdx.x;
    int tile = i / (KT * 16);
    int ti   = i % (KT * 16);
    int k2 = ti >> 5;
    int np = (ti & 31) >> 1, jp = ti & 1;
    int kg = 2 * k2 + jp;
    int u  = np >> 1;
    int gA = 2 * (np & 1);
    int j  = tile * 8 + u;
    const float* row = (kg < KX) ? (Wx + (size_t)kg * (4 * Hh))
                                 : (Wh + (size_t)(kg - KX) * (4 * Hh));
    dst[i] = pack2(row[gA * Hh + j], row[(gA + 1) * Hh + j]);
}

// ---------------- Wd transpose + bf16 split (one-time) ----------------
__global__ __launch_bounds__(256) void transpose_wd(const float* __restrict__ Wd) {
    __shared__ float ts[32][33];
    int n0 = blockIdx.x * 32, k0 = blockIdx.y * 32;
    int c = threadIdx.x & 31, r8 = threadIdx.x >> 5;
#pragma unroll
    for (int p = 0; p < 4; p++) {
        int k = k0 + r8 + p * 8;
        ts[r8 + p * 8][c] = Wd[(size_t)k * DVv + n0 + c];
    }
    __syncthreads();
#pragma unroll
    for (int p = 0; p < 4; p++) {
        int n = n0 + r8 + p * 8;
        float v = ts[c][r8 + p * 8];
        __nv_bfloat16 hi = __float2bfloat16(v);
        float rem = v - __bfloat162float(hi);
        g_WdtHi[(size_t)n * Hh + k0 + c] = hi;
        g_WdtLo[(size_t)n * Hh + k0 + c] = __float2bfloat16(rem);
    }
}

// ---------------- Hall bf16 split (after recurrence) ----------------
__global__ __launch_bounds__(256) void split_hall() {
    int i = blockIdx.x * 256 + threadIdx.x;
    float a = g_Hall[i];
    __nv_bfloat16 hi = __float2bfloat16(a);
    float rem = a - __bfloat162float(hi);
    g_HallHi[i] = hi;
    g_HallLo[i] = __float2bfloat16(rem);
}

// ---------------- enc-proj fp32 SGEMM (R7-proven) ----------------
__global__ __launch_bounds__(256) void sgemm_enc(const float* __restrict__ Am,
                                                 const float* __restrict__ Bm,
                                                 const float* __restrict__ bias) {
    constexpr int K = 512, N = Aa;
    float* Cm = g_encproj;

    __shared__ __align__(16) float As[16][64];
    __shared__ __align__(16) float Bs[16][64];

    const int tid = threadIdx.x;
    const int rowbase = blockIdx.y * 64;
    const int colbase = blockIdx.x * 64;

    const int lr  = tid >> 2;
    const int lkq = tid & 3;
    const int lk  = tid >> 4;
    const int lnq = tid & 15;
    const float* Ap = Am + (size_t)(rowbase + lr) * K + lkq * 4;
    const float* Bp = Bm + (size_t)lk * N + colbase + lnq * 4;

    const int mt = tid >> 4, nt = tid & 15;
    const int m0 = mt * 4, n0 = nt * 4;

    ull acc[2][4];
#pragma unroll
    for (int i = 0; i < 2; i++)
#pragma unroll
        for (int j = 0; j < 4; j++) acc[i][j] = 0ull;

    for (int kb = 0; kb < K; kb += 16) {
        float4 av = *(const float4*)(Ap + kb);
        float4 bv = *(const float4*)(Bp + (size_t)kb * N);
        __syncthreads();
        As[lkq * 4 + 0][lr] = av.x;
        As[lkq * 4 + 1][lr] = av.y;
        As[lkq * 4 + 2][lr] = av.z;
        As[lkq * 4 + 3][lr] = av.w;
        *(float4*)&Bs[lk][lnq * 4] = bv;
        __syncthreads();
#pragma unroll
        for (int k = 0; k < 16; k++) {
            ulonglong2 ap = *(const ulonglong2*)&As[k][m0];
            float4 b = *(const float4*)&Bs[k][n0];
            ull b0 = pack2(b.x, b.x), b1p = pack2(b.y, b.y);
            ull b2p = pack2(b.z, b.z), b3p = pack2(b.w, b.w);
            ffma2(acc[0][0], ap.x, b0);  ffma2(acc[1][0], ap.y, b0);
            ffma2(acc[0][1], ap.x, b1p); ffma2(acc[1][1], ap.y, b1p);
            ffma2(acc[0][2], ap.x, b2p); ffma2(acc[1][2], ap.y, b2p);
            ffma2(acc[0][3], ap.x, b3p); ffma2(acc[1][3], ap.y, b3p);
        }
    }

#pragma unroll
    for (int j = 0; j < 4; j++) {
        int col = colbase + n0 + j;
        float bj = bias[col];
        float2 v0 = unpack2(acc[0][j]);
        float2 v1 = unpack2(acc[1][j]);
        float vals[4] = {v0.x, v0.y, v1.x, v1.y};
#pragma unroll
        for (int i = 0; i < 4; i++) {
            int r = rowbase + m0 + i;
            Cm[(size_t)r * N + col] = vals[i] + bj;
        }
    }
}

// ---------------- fused Bahdanau attention + input concat (1 block / batch) ----
__global__ __launch_bounds__(512) void attention_step(
    const float* __restrict__ enc, const float* __restrict__ W1,
    const float* __restrict__ b1, const float* __restrict__ V,
    const float* __restrict__ bV, const float* __restrict__ tokens,
    int rp, int t) {
    __shared__ float h1s[Hh], qs[Aa], Vs[Aa];
    __shared__ float qred[4][Aa];
    __shared__ float sc[Ss], at[Ss];

    const int b = blockIdx.x, tid = threadIdx.x;
    const float* H1 = g_h1[rp] + b * Hh;
    h1s[tid] = H1[tid];
    Vs[tid] = V[tid];
    __syncthreads();

    {
        int jq = tid & 127, ks = tid >> 7;
        int j4 = jq * 4;
        float a0 = 0.f, a1 = 0.f, a2 = 0.f, a3 = 0.f;
        int kend = ks * 128 + 128;
#pragma unroll 4
        for (int k = ks * 128; k < kend; k++) {
            float hv = h1s[k];
            float4 wv = *(const float4*)(W1 + (size_t)k * Aa + j4);
            a0 += hv * wv.x; a1 += hv * wv.y; a2 += hv * wv.z; a3 += hv * wv.w;
        }
        qred[ks][j4]     = a0; qred[ks][j4 + 1] = a1;
        qred[ks][j4 + 2] = a2; qred[ks][j4 + 3] = a3;
    }
    __syncthreads();
    qs[tid] = qred[0][tid] + qred[1][tid] + qred[2][tid] + qred[3][tid] + b1[tid];
    __syncthreads();

    const int warp = tid >> 5, lane = tid & 31;
    const float* ep = g_encproj + (size_t)b * Ss * Aa;
    for (int s = warp; s < Ss; s += 16) {
        float p = 0.f;
        const float* eps = ep + s * Aa;
#pragma unroll 4
        for (int a0 = lane; a0 < Aa; a0 += 32)
            p += tanh_fast(eps[a0] + qs[a0]) * Vs[a0];
#pragma unroll
        for (int o = 16; o; o >>= 1) p += __shfl_xor_sync(0xffffffffu, p, o);
        if (lane == 0) sc[s] = p + bV[0];
    }
    __syncthreads();

    if (warp == 0) {
        float s0 = sc[lane], s1 = sc[lane + 32];
        float mx = fmaxf(s0, s1);
#pragma unroll
        for (int o = 16; o; o >>= 1) mx = fmaxf(mx, __shfl_xor_sync(0xffffffffu, mx, o));
        float e0 = expf(s0 - mx), e1 = expf(s1 - mx);
        float sm = e0 + e1;
#pragma unroll
        for (int o = 16; o; o >>= 1) sm += __shfl_xor_sync(0xffffffffu, sm, o);
        float inv = 1.f / sm;
        at[lane] = e0 * inv;
        at[lane + 32] = e1 * inv;
    }
    __syncthreads();

    const float* eb = enc + (size_t)b * Ss * Hh;
    float c = 0.f;
#pragma unroll 8
    for (int s = 0; s < Ss; s++) c += at[s] * eb[s * Hh + tid];
    float* x0 = g_x0 + b * (Hh + Ee);
    x0[tid] = c;
    if (tid < Ee) x0[Hh + tid] = tokens[((size_t)b * Tt + t) * Ee + tid];
}

// ---------------- fused LSTM step: full-K GEMM + in-block gates ----------
// 64 blocks x 256 threads. Block bx owns 32 z-cols = 8 units x 4 gates
// (gate-interleaved repack), all 32 batches, FULL K. No split-K, no
// atomics: state updates are block-exclusive and deterministic.
// x staged per 128-k chunk, dup-packed. Smem layout: part-stride 4624B
// (=36*128+16 -> 16*part mod 128 distinct: STS.128 phases conflict-free),
// row-stride 144B (16B-aligned). Reads are broadcast (whole warp same addr).
#define XPART 4624
#define XROW  144
template<int LAYER>
__global__ __launch_bounds__(256) void lstm_full(int rp, int t,
        const float* __restrict__ bias) {
    constexpr int NCH = LAYER ? 8 : 10;          // 128-k chunks
    constexpr int KX  = LAYER ? Hh : (Hh + Ee);  // 512 / 768 (chunk-aligned)
    const ull* wt = (LAYER ? g_wpk1 : g_wpk0)
                  + (size_t)blockIdx.x * (NCH * 128) * 16;
    const float* X     = LAYER ? g_h0[1 - rp] : g_x0;
    const float* Hprev = LAYER ? g_h1[rp]     : g_h0[rp];

    __shared__ __align__(16) char xs[8 * XPART]; // 36,992 B
    __shared__ float Zs[32][33];

    const int tid = threadIdx.x;
    const int bx  = blockIdx.x;
    const int np = tid & 15, ms = tid >> 4;      // compute mapping
    const int sm = tid >> 3, sp = tid & 7;       // staging mapping

    const ulonglong2* wp = (const ulonglong2*)wt + np;
    const char* xra = xs + ms * XROW;
    const char* xrb = xs + (ms + 16) * XROW;

    ull acc0 = 0ull, acc1 = 0ull;
    for (int ci = 0; ci < NCH; ci++) {
        {   // stage: 16 k-values per thread, dup-packed
            int kb = ci * 128 + sp * 16;
            const float* src = (kb < KX) ? (X + (size_t)sm * KX + kb)
                                         : (Hprev + (size_t)sm * Hh + (kb - KX));
            char* dst = xs + sp * XPART + sm * XROW;
#pragma unroll
            for (int q4 = 0; q4 < 4; q4++) {
                float4 v = *(const float4*)(src + q4 * 4);
                ulonglong2 w0, w1;
                w0.x = pack2(v.x, v.x); w0.y = pack2(v.y, v.y);
                w1.x = pack2(v.z, v.z); w1.y = pack2(v.w, v.w);
                *(ulonglong2*)(dst + q4 * 32)      = w0;
                *(ulonglong2*)(dst + q4 * 32 + 16) = w1;
            }
        }
        __syncthreads();
        const int cbase = ci * 64;
#pragma unroll 8
        for (int k2l = 0; k2l < 64; k2l++) {
            ulonglong2 w = wp[(size_t)(cbase + k2l) * 16];
            const int xo = (k2l >> 3) * XPART + ((2 * k2l) & 15) * 8;
            ulonglong2 a = *(const ulonglong2*)(xra + xo);
            ulonglong2 b = *(const ulonglong2*)(xrb + xo);
            ffma2(acc0, a.x, w.x);
            ffma2(acc1, b.x, w.x);
            ffma2(acc0, a.y, w.y);
            ffma2(acc1, b.y, w.y);
        }
        __syncthreads();
    }

    {   // stage z tile
        float2 v;
        v = unpack2(acc0); Zs[ms][2 * np] = v.x;      Zs[ms][2 * np + 1] = v.y;
        v = unpack2(acc1); Zs[ms + 16][2 * np] = v.x; Zs[ms + 16][2 * np + 1] = v.y;
    }
    __syncthreads();

    {   // gates: 32 m x 8 units, block-exclusive state
        int m = tid >> 3, u = tid & 7;
        int j = bx * 8 + u;
        float zi = Zs[m][u * 4 + 0] + bias[j];
        float zf = Zs[m][u * 4 + 1] + bias[Hh + j];
        float zg = Zs[m][u * 4 + 2] + bias[2 * Hh + j];
        float zo = Zs[m][u * 4 + 3] + bias[3 * Hh + j];
        float ig = 1.f / (1.f + expf(-zi));
        float fg = 1.f / (1.f + expf(-zf));
        float og = 1.f / (1.f + expf(-zo));
        float* C    = LAYER ? g_c1 : g_c0;
        float* Hout = LAYER ? g_h1[1 - rp] : g_h0[1 - rp];
        int idx = m * Hh + j;
        float cn = fg * C[idx] + ig * tanhf(zg);
        float hn = og * tanhf(cn);
        C[idx] = cn;
        Hout[idx] = hn;
        if (LAYER == 1) g_Hall[((size_t)t * Bb + m) * Hh + j] = hn;
    }
}

// ---------------- logits: mma.sync bf16 split GEMM (R12-proven) ----------
#define LROW 80
#define LOPSZ (128 * LROW)
#define LBUF  (4 * LOPSZ)

__global__ __launch_bounds__(256, 1) void logits_tc(const float* __restrict__ bd,
                                                    float* __restrict__ out) {
    extern __shared__ __align__(16) char lsm[];
    const int tid = threadIdx.x;
    const int wid = tid >> 5, lane = tid & 31;
    const int colbase = blockIdx.x * 128;
    const int rowbase = blockIdx.y * 128;
    const int wm = wid >> 2, wn = wid & 3;

    const unsigned smbase = smem_u32(lsm);

    const int sr = tid >> 1, part = tid & 1;
    const uint4* gAH = (const uint4*)(g_HallHi + (size_t)(rowbase + sr) * Hh) + part * 2;
    const uint4* gAL = (const uint4*)(g_HallLo + (size_t)(rowbase + sr) * Hh) + part * 2;
    const uint4* gBH = (const uint4*)(g_WdtHi + (size_t)(colbase + sr) * Hh) + part * 2;
    const uint4* gBL = (const uint4*)(g_WdtLo + (size_t)(colbase + sr) * Hh) + part * 2;
    const unsigned sdst = sr * LROW + part * 32;

    float d[4][4][4];
#pragma unroll
    for (int mi = 0; mi < 4; mi++)
#pragma unroll
        for (int ni = 0; ni < 4; ni++)
#pragma unroll
            for (int q = 0; q < 4; q++) d[mi][ni][q] = 0.f;

    const unsigned aoff = (lane & 15) * LROW + (lane >> 4) * 16;
    const unsigned boff = ((lane & 7) + ((lane >> 4) << 3)) * LROW
                        + (((lane >> 3) & 1) << 4);

    uint4 rAH0 = gAH[0], rAH1 = gAH[1];
    uint4 rAL0 = gAL[0], rAL1 = gAL[1];
    uint4 rBH0 = gBH[0], rBH1 = gBH[1];
    uint4 rBL0 = gBL[0], rBL1 = gBL[1];
    {
        char* bb = lsm + sdst;
        *(uint4*)(bb + 0 * LOPSZ)      = rAH0; *(uint4*)(bb + 0 * LOPSZ + 16) = rAH1;
        *(uint4*)(bb + 1 * LOPSZ)      = rAL0; *(uint4*)(bb + 1 * LOPSZ + 16) = rAL1;
        *(uint4*)(bb + 2 * LOPSZ)      = rBH0; *(uint4*)(bb + 2 * LOPSZ + 16) = rBH1;
        *(uint4*)(bb + 3 * LOPSZ)      = rBL0; *(uint4*)(bb + 3 * LOPSZ + 16) = rBL1;
    }
    __syncthreads();

    for (int c = 0; c < 16; c++) {
        const int p = c & 1;
        if (c < 15) {
            int o = (c + 1) * 4;
            rAH0 = gAH[o]; rAH1 = gAH[o + 1];
            rAL0 = gAL[o]; rAL1 = gAL[o + 1];
            rBH0 = gBH[o]; rBH1 = gBH[o + 1];
            rBL0 = gBL[o]; rBL1 = gBL[o + 1];
        }

        const unsigned bAH = smbase + p * LBUF + 0 * LOPSZ;
        const unsigned bAL = smbase + p * LBUF + 1 * LOPSZ;
        const unsigned bBH = smbase + p * LBUF + 2 * LOPSZ;
        const unsigned bBL = smbase + p * LBUF + 3 * LOPSZ;

#pragma unroll
        for (int ks = 0; ks < 2; ks++) {
            unsigned aHi[4][4], aLo[4][4], bHi[4][2], bLo[4][2];
#pragma unroll
            for (int mi = 0; mi < 4; mi++) {
                unsigned r = (wm * 64 + mi * 16) * LROW + ks * 32;
                ldsm4(aHi[mi], bAH + r + aoff);
                ldsm4(aLo[mi], bAL + r + aoff);
            }
#pragma unroll
            for (int nh = 0; nh < 2; nh++) {
                unsigned r = (wn * 32 + nh * 16) * LROW + ks * 32;
                unsigned t4[4];
                ldsm4(t4, bBH + r + boff);
                bHi[nh * 2][0] = t4[0]; bHi[nh * 2][1] = t4[1];
                bHi[nh * 2 + 1][0] = t4[2]; bHi[nh * 2 + 1][1] = t4[3];
                ldsm4(t4, bBL + r + boff);
                bLo[nh * 2][0] = t4[0]; bLo[nh * 2][1] = t4[1];
                bLo[nh * 2 + 1][0] = t4[2]; bLo[nh * 2 + 1][1] = t4[3];
            }
#pragma unroll
            for (int mi = 0; mi < 4; mi++)
#pragma unroll
                for (int ni = 0; ni < 4; ni++) {
                    mma16816(d[mi][ni], aHi[mi], bHi[ni]);
                    mma16816(d[mi][ni], aHi[mi], bLo[ni]);
                    mma16816(d[mi][ni], aLo[mi], bHi[ni]);
                }
        }

        if (c < 15) {
            char* bb = lsm + ((c + 1) & 1) * LBUF + sdst;
            *(uint4*)(bb + 0 * LOPSZ)      = rAH0; *(uint4*)(bb + 0 * LOPSZ + 16) = rAH1;
            *(uint4*)(bb + 1 * LOPSZ)      = rAL0; *(uint4*)(bb + 1 * LOPSZ + 16) = rAL1;
            *(uint4*)(bb + 2 * LOPSZ)      = rBH0; *(uint4*)(bb + 2 * LOPSZ + 16) = rBH1;
            *(uint4*)(bb + 3 * LOPSZ)      = rBL0; *(uint4*)(bb + 3 * LOPSZ + 16) = rBL1;
            __syncthreads();
        }
    }

    const int g = lane >> 2, tg = lane & 3;
#pragma unroll
    for (int mi = 0; mi < 4; mi++) {
#pragma unroll
        for (int half = 0; half < 2; half++) {
            int r = rowbase + wm * 64 + mi * 16 + g + half * 8;
            int orow = (r & 31) * Tt + (r >> 5);
            float* op = out + (size_t)orow * DVv;
#pragma unroll
            for (int ni = 0; ni < 4; ni++) {
                int col = colbase + wn * 32 + ni * 8 + tg * 2;
                float2 bj = *(const float2*)(bd + col);
                float2 v;
                v.x = d[mi][ni][half * 2 + 0] + bj.x;
                v.y = d[mi][ni][half * 2 + 1] + bj.y;
                *(float2*)(op + col) = v;
            }
        }
    }
}

// ---------------- launch ----------------
extern "C" void kernel_launch(void* const* d_in, const int* in_sizes, int n_in,
                              void* d_out, int out_size) {
    const float* initial_input  = (const float*)d_in[0];
    const float* hidden0        = (const float*)d_in[1];
    const float* cell0          = (const float*)d_in[2];
    const float* encoder_output = (const float*)d_in[3];
    const float* W1 = (const float*)d_in[4];
    const float* b1 = (const float*)d_in[5];
    const float* W2 = (const float*)d_in[6];
    const float* b2 = (const float*)d_in[7];
    const float* V  = (const float*)d_in[8];
    const float* bV = (const float*)d_in[9];
    const float* Wx0 = (const float*)d_in[10];
    const float* Wh0 = (const float*)d_in[11];
    const float* bL0 = (const float*)d_in[12];
    const float* Wx1 = (const float*)d_in[13];
    const float* Wh1 = (const float*)d_in[14];
    const float* bL1 = (const float*)d_in[15];
    const float* Wd  = (const float*)d_in[16];
    const float* bd  = (const float*)d_in[17];
    float* out = (float*)d_out;

    cudaFuncSetAttribute(logits_tc, cudaFuncAttributeMaxDynamicSharedMemorySize,
                         2 * LBUF);

    init_state<<<(Bb * Hh + 255) / 256, 256>>>(hidden0, cell0);

    repack_w<0><<<(64 * 1280 * 16) / 256, 256>>>(Wx0, Wh0);
    repack_w<1><<<(64 * 1024 * 16) / 256, 256>>>(Wx1, Wh1);
    transpose_wd<<<dim3(DVv / 32, Hh / 32), 256>>>(Wd);

    sgemm_enc<<<dim3(Aa / 64, (Bb * Ss) / 64), 256>>>(encoder_output, W2, b2);

    for (int t = 0; t < Tt; t++) {
        int rp = t & 1;
        attention_step<<<Bb, 512>>>(encoder_output, W1, b1, V, bV,
                                    initial_input, rp, t);
        lstm_full<0><<<64, 256>>>(rp, t, bL0);
        lstm_full<1><<<64, 256>>>(rp, t, bL1);
    }

    split_hall<<<(Tt * Bb * Hh) / 256, 256>>>();
    logits_tc<<<dim3(DVv / 128, (Tt * Bb) / 128), 256, 2 * LBUF>>>(bd, out);

    long long total = (long long)Bb * Tt * DVv;
    if ((long long)out_size >= total + 4LL * Bb * Hh)
        write_tail<<<(Bb * Hh + 255) / 256, 256>>>(out + total);
}

// round 15
// speedup vs baseline: 1.7910x; 1.7910x over previous
#include <cuda_runtime.h>
#include <cuda_bf16.h>
#include <math.h>

typedef unsigned long long ull;

#define Bb 32
#define Tt 64
#define Ss 64
#define Ee 256
#define Hh 512
#define Aa 512
#define DVv 32000

// ---------------- device scratch (no allocation allowed) ----------------
__device__ float g_encproj[Bb * Ss * Aa];        // 4 MB
__device__ float g_h0[2][Bb * Hh];
__device__ float g_h1[2][Bb * Hh];
__device__ float g_c0[Bb * Hh];
__device__ float g_c1[Bb * Hh];
__device__ float g_x0[Bb * (Hh + Ee)];
__device__ float g_zpart[8 * Bb * 4 * Hh];       // 2 MB split-K partials
// repacked LSTM weights: per (bx, ksb) tile, [k2][np][2] ull pairs
__device__ ull g_wpk0[64 * 8 * 160 * 16];        // 10.5 MB (K=1280)
__device__ ull g_wpk1[64 * 8 * 128 * 16];        // 8.4 MB  (K=1024)
// logits tensor-core operands (bf16 2-term split); h1 history stored here
__device__ __nv_bfloat16 g_HallHi[Tt * Bb * Hh]; // 2 MB
__device__ __nv_bfloat16 g_HallLo[Tt * Bb * Hh]; // 2 MB
__device__ __nv_bfloat16 g_WdtHi[(size_t)DVv * Hh]; // 32.8 MB, [n][k]
__device__ __nv_bfloat16 g_WdtLo[(size_t)DVv * Hh]; // 32.8 MB

// ---------------- packed fp32x2 helpers (Blackwell FFMA2) ----------------
__device__ __forceinline__ void ffma2(ull &c, ull a, ull b) {
    asm("fma.rn.f32x2 %0, %1, %2, %0;" : "+l"(c) : "l"(a), "l"(b));
}
__device__ __forceinline__ ull pack2(float x, float y) {
    ull r; asm("mov.b64 %0, {%1, %2};" : "=l"(r) : "f"(x), "f"(y)); return r;
}
__device__ __forceinline__ float2 unpack2(ull v) {
    float2 f; asm("mov.b64 {%0, %1}, %2;" : "=f"(f.x), "=f"(f.y) : "l"(v)); return f;
}
__device__ __forceinline__ float tanh_fast(float x) {
    float y; asm("tanh.approx.f32 %0, %1;" : "=f"(y) : "f"(x)); return y;
}
__device__ __forceinline__ unsigned smem_u32(const void* p) {
    unsigned a;
    asm("{ .reg .u64 t; cvta.to.shared.u64 t, %1; cvt.u32.u64 %0, t; }"
        : "=r"(a) : "l"(p));
    return a;
}

// ---------------- mma.sync helpers (arch-neutral tensor core path) ----------
__device__ __forceinline__ void ldsm4(unsigned* r, unsigned addr) {
    asm volatile("ldmatrix.sync.aligned.m8n8.x4.shared.b16 {%0,%1,%2,%3}, [%4];"
                 : "=r"(r[0]), "=r"(r[1]), "=r"(r[2]), "=r"(r[3]) : "r"(addr));
}
__device__ __forceinline__ void mma16816(float* d, const unsigned* a,
                                         const unsigned* b) {
    asm volatile(
        "mma.sync.aligned.m16n8k16.row.col.f32.bf16.bf16.f32 "
        "{%0,%1,%2,%3}, {%4,%5,%6,%7}, {%8,%9}, {%0,%1,%2,%3};"
        : "+f"(d[0]), "+f"(d[1]), "+f"(d[2]), "+f"(d[3])
        : "r"(a[0]), "r"(a[1]), "r"(a[2]), "r"(a[3]), "r"(b[0]), "r"(b[1]));
}

// ---------------- init / tail ----------------
__global__ void init_state(const float* __restrict__ hidden0,
                           const float* __restrict__ cell0) {
    int i = blockIdx.x * 256 + threadIdx.x;
    if (i < Bb * Hh) {
        g_h0[0][i] = hidden0[i];
        g_h1[0][i] = hidden0[Bb * Hh + i];
        g_c0[i]    = cell0[i];
        g_c1[i]    = cell0[Bb * Hh + i];
    }
}

__global__ void write_tail(float* __restrict__ out) {
    int i = blockIdx.x * 256 + threadIdx.x;
    const int fin = (Tt & 1);  // T=64 -> final h lives in buffer 0
    if (i < Bb * Hh) {
        out[i]               = g_h0[fin][i];
        out[Bb * Hh + i]     = g_h1[fin][i];
        out[2 * Bb * Hh + i] = g_c0[i];
        out[3 * Bb * Hh + i] = g_c1[i];
    }
}

// ---------------- weight repack: [Wx;Wh] -> tile-contiguous pair layout ----
template<int LAYER>
__global__ __launch_bounds__(256) void repack_w(const float* __restrict__ Wx,
                                                const float* __restrict__ Wh) {
    constexpr int KX = LAYER ? Hh : (Hh + Ee);
    constexpr int CH = (KX + Hh) / 8;
    ull* dst = LAYER ? g_wpk1 : g_wpk0;
    int i = blockIdx.x * 256 + threadIdx.x;
    int tile = i / (CH * 16);
    int ti   = i % (CH * 16);
    int bx = tile >> 3, ksb = tile & 7;
    int k2 = ti >> 5;
    int np = (ti & 31) >> 1, j = ti & 1;
    int kg = ksb * CH + 2 * k2 + j;
    int colp = bx * 16 + np;
    const ull* src = (kg < KX)
        ? (const ull*)Wx + (size_t)kg * 1024 + colp
        : (const ull*)Wh + (size_t)(kg - KX) * 1024 + colp;
    dst[i] = *src;
}

// ---------------- Wd transpose + bf16 split (one-time) ----------------
__global__ __launch_bounds__(256) void transpose_wd(const float* __restrict__ Wd) {
    __shared__ float ts[32][33];
    int n0 = blockIdx.x * 32, k0 = blockIdx.y * 32;
    int c = threadIdx.x & 31, r8 = threadIdx.x >> 5;
#pragma unroll
    for (int p = 0; p < 4; p++) {
        int k = k0 + r8 + p * 8;
        ts[r8 + p * 8][c] = Wd[(size_t)k * DVv + n0 + c];
    }
    __syncthreads();
#pragma unroll
    for (int p = 0; p < 4; p++) {
        int n = n0 + r8 + p * 8;
        float v = ts[c][r8 + p * 8];
        __nv_bfloat16 hi = __float2bfloat16(v);
        float rem = v - __bfloat162float(hi);
        g_WdtHi[(size_t)n * Hh + k0 + c] = hi;
        g_WdtLo[(size_t)n * Hh + k0 + c] = __float2bfloat16(rem);
    }
}

// ---------------- enc-proj fp32 SGEMM (R7-proven) ----------------
__global__ __launch_bounds__(256) void sgemm_enc(const float* __restrict__ Am,
                                                 const float* __restrict__ Bm,
                                                 const float* __restrict__ bias) {
    constexpr int K = 512, N = Aa;
    float* Cm = g_encproj;

    __shared__ __align__(16) float As[16][64];
    __shared__ __align__(16) float Bs[16][64];

    const int tid = threadIdx.x;
    const int rowbase = blockIdx.y * 64;
    const int colbase = blockIdx.x * 64;

    const int lr  = tid >> 2;
    const int lkq = tid & 3;
    const int lk  = tid >> 4;
    const int lnq = tid & 15;
    const float* Ap = Am + (size_t)(rowbase + lr) * K + lkq * 4;
    const float* Bp = Bm + (size_t)lk * N + colbase + lnq * 4;

    const int mt = tid >> 4, nt = tid & 15;
    const int m0 = mt * 4, n0 = nt * 4;

    ull acc[2][4];
#pragma unroll
    for (int i = 0; i < 2; i++)
#pragma unroll
        for (int j = 0; j < 4; j++) acc[i][j] = 0ull;

    for (int kb = 0; kb < K; kb += 16) {
        float4 av = *(const float4*)(Ap + kb);
        float4 bv = *(const float4*)(Bp + (size_t)kb * N);
        __syncthreads();
        As[lkq * 4 + 0][lr] = av.x;
        As[lkq * 4 + 1][lr] = av.y;
        As[lkq * 4 + 2][lr] = av.z;
        As[lkq * 4 + 3][lr] = av.w;
        *(float4*)&Bs[lk][lnq * 4] = bv;
        __syncthreads();
#pragma unroll
        for (int k = 0; k < 16; k++) {
            ulonglong2 ap = *(const ulonglong2*)&As[k][m0];
            float4 b = *(const float4*)&Bs[k][n0];
            ull b0 = pack2(b.x, b.x), b1p = pack2(b.y, b.y);
            ull b2p = pack2(b.z, b.z), b3p = pack2(b.w, b.w);
            ffma2(acc[0][0], ap.x, b0);  ffma2(acc[1][0], ap.y, b0);
            ffma2(acc[0][1], ap.x, b1p); ffma2(acc[1][1], ap.y, b1p);
            ffma2(acc[0][2], ap.x, b2p); ffma2(acc[1][2], ap.y, b2p);
            ffma2(acc[0][3], ap.x, b3p); ffma2(acc[1][3], ap.y, b3p);
        }
    }

#pragma unroll
    for (int j = 0; j < 4; j++) {
        int col = colbase + n0 + j;
        float bj = bias[col];
        float2 v0 = unpack2(acc[0][j]);
        float2 v1 = unpack2(acc[1][j]);
        float vals[4] = {v0.x, v0.y, v1.x, v1.y};
#pragma unroll
        for (int i = 0; i < 4; i++) {
            int r = rowbase + m0 + i;
            Cm[(size_t)r * N + col] = vals[i] + bj;
        }
    }
}

// ---------------- attention + fused LSTM1 gate prologue (1 block / batch) ----
// For t>0: block b first finishes layer-1 gates of step t-1 for ITS batch only
// (reduces the 8 zpart partials in fixed ksb order -> bit-identical to the old
// lstm_gates), updates c1/h1 (block-exclusive), writes bf16 hi/lo h1-history,
// and feeds h1 straight into the q-GEMM smem. Saves one kernel launch per step
// plus the separate split_hall pass.
__global__ __launch_bounds__(512) void attention_step(
    const float* __restrict__ enc, const float* __restrict__ W1,
    const float* __restrict__ b1, const float* __restrict__ V,
    const float* __restrict__ bV, const float* __restrict__ tokens,
    const float* __restrict__ bL1, int rp, int t, int dopro) {
    __shared__ float h1s[Hh], qs[Aa], Vs[Aa];
    __shared__ float qred[4][Aa];
    __shared__ float sc[Ss], at[Ss];

    const int b = blockIdx.x, tid = threadIdx.x;
    Vs[tid] = V[tid];
    if (dopro) {
        float zi = bL1[tid], zf = bL1[Hh + tid];
        float zg = bL1[2 * Hh + tid], zo = bL1[3 * Hh + tid];
#pragma unroll
        for (int ksb = 0; ksb < 8; ksb++) {
            const float* zr = g_zpart + (ksb * 32 + b) * 2048;
            zi += zr[tid];
            zf += zr[Hh + tid];
            zg += zr[2 * Hh + tid];
            zo += zr[3 * Hh + tid];
        }
        float ig = 1.f / (1.f + expf(-zi));
        float fg = 1.f / (1.f + expf(-zf));
        float og = 1.f / (1.f + expf(-zo));
        int idx = b * Hh + tid;
        float cn = fg * g_c1[idx] + ig * tanhf(zg);
        float hn = og * tanhf(cn);
        g_c1[idx] = cn;
        g_h1[rp][idx] = hn;
        __nv_bfloat16 hi = __float2bfloat16(hn);
        size_t hrow = ((size_t)(t - 1) * Bb + b) * Hh + tid;
        g_HallHi[hrow] = hi;
        g_HallLo[hrow] = __float2bfloat16(hn - __bfloat162float(hi));
        h1s[tid] = hn;
    } else {
        h1s[tid] = g_h1[rp][b * Hh + tid];
    }
    __syncthreads();

    {
        int jq = tid & 127, ks = tid >> 7;
        int j4 = jq * 4;
        float a0 = 0.f, a1 = 0.f, a2 = 0.f, a3 = 0.f;
        int kend = ks * 128 + 128;
#pragma unroll 4
        for (int k = ks * 128; k < kend; k++) {
            float hv = h1s[k];
            float4 wv = *(const float4*)(W1 + (size_t)k * Aa + j4);
            a0 += hv * wv.x; a1 += hv * wv.y; a2 += hv * wv.z; a3 += hv * wv.w;
        }
        qred[ks][j4]     = a0; qred[ks][j4 + 1] = a1;
        qred[ks][j4 + 2] = a2; qred[ks][j4 + 3] = a3;
    }
    __syncthreads();
    qs[tid] = qred[0][tid] + qred[1][tid] + qred[2][tid] + qred[3][tid] + b1[tid];
    __syncthreads();

    const int warp = tid >> 5, lane = tid & 31;
    const float* ep = g_encproj + (size_t)b * Ss * Aa;
    for (int s = warp; s < Ss; s += 16) {
        float p = 0.f;
        const float* eps = ep + s * Aa;
#pragma unroll 4
        for (int a0 = lane; a0 < Aa; a0 += 32)
            p += tanh_fast(eps[a0] + qs[a0]) * Vs[a0];
#pragma unroll
        for (int o = 16; o; o >>= 1) p += __shfl_xor_sync(0xffffffffu, p, o);
        if (lane == 0) sc[s] = p + bV[0];
    }
    __syncthreads();

    if (warp == 0) {
        float s0 = sc[lane], s1 = sc[lane + 32];
        float mx = fmaxf(s0, s1);
#pragma unroll
        for (int o = 16; o; o >>= 1) mx = fmaxf(mx, __shfl_xor_sync(0xffffffffu, mx, o));
        float e0 = expf(s0 - mx), e1 = expf(s1 - mx);
        float sm = e0 + e1;
#pragma unroll
        for (int o = 16; o; o >>= 1) sm += __shfl_xor_sync(0xffffffffu, sm, o);
        float inv = 1.f / sm;
        at[lane] = e0 * inv;
        at[lane + 32] = e1 * inv;
    }
    __syncthreads();

    const float* eb = enc + (size_t)b * Ss * Hh;
    float c = 0.f;
#pragma unroll 8
    for (int s = 0; s < Ss; s++) c += at[s] * eb[s * Hh + tid];
    float* x0 = g_x0 + b * (Hh + Ee);
    x0[tid] = c;
    if (tid < Ee) x0[Hh + tid] = tokens[((size_t)b * Tt + t) * Ee + tid];
}

// ---------------- LSTM matmul: split-K, repacked weights (R7-proven) ---------
template<int LAYER>
__global__ __launch_bounds__(256) void lstm_mm(int rp) {
    constexpr int KX  = LAYER ? Hh : (Hh + Ee);   // 512 or 768
    constexpr int CH  = (KX + Hh) / 8;            // 128 or 160
    constexpr int C2  = CH / 2;
    constexpr int STR = CH + 2;
    const float* X     = LAYER ? g_h0[1 - rp] : g_x0;
    const float* Hprev = LAYER ? g_h1[rp]     : g_h0[rp];
    const ull* wpk     = LAYER ? g_wpk1       : g_wpk0;

    __shared__ __align__(16) ull xd[32 * STR];

    const int tid = threadIdx.x;
    const int ksb = blockIdx.y;
    const int k0  = ksb * CH;
    const int bx  = blockIdx.x;
    const int c0  = bx * 32;

    {
        int m = tid >> 3;
        int part = tid & 7;
        constexpr int PER = CH / 8;
        int kb = part * PER;
        const float* xrow = X + (size_t)m * KX;
        const float* hrow = Hprev + m * Hh;
        ull* dst = xd + m * STR + kb;
#pragma unroll
        for (int q = 0; q < PER; q += 4) {
            int kg = k0 + kb + q;
            float4 v = (kg < KX) ? *(const float4*)(xrow + kg)
                                 : *(const float4*)(hrow + (kg - KX));
            dst[q + 0] = pack2(v.x, v.x);
            dst[q + 1] = pack2(v.y, v.y);
            dst[q + 2] = pack2(v.z, v.z);
            dst[q + 3] = pack2(v.w, v.w);
        }
    }
    __syncthreads();

    const int np = tid & 15;
    const int ms = tid >> 4;

    const ulonglong2* wp = (const ulonglong2*)(wpk + (size_t)(bx * 8 + ksb) * (CH * 16)) + np;
    const ulonglong2* xap = (const ulonglong2*)(xd + ms * STR);
    const ulonglong2* xbp = (const ulonglong2*)(xd + (ms + 16) * STR);

    ull acc0 = 0ull, acc1 = 0ull;
#pragma unroll 8
    for (int k2 = 0; k2 < C2; k2++) {
        ulonglong2 w = wp[k2 * 16];
        ulonglong2 a = xap[k2];
        ulonglong2 b = xbp[k2];
        ffma2(acc0, a.x, w.x);
        ffma2(acc1, b.x, w.x);
        ffma2(acc0, a.y, w.y);
        ffma2(acc1, b.y, w.y);
    }

    *(ull*)&g_zpart[((ksb * 32 + ms) * 2048) + c0 + 2 * np]      = acc0;
    *(ull*)&g_zpart[((ksb * 32 + ms + 16) * 2048) + c0 + 2 * np] = acc1;
}

// ---------------- gate epilogue (layer 0 every step; layer 1 only final) -----
__global__ __launch_bounds__(256) void lstm_gates(int layer, int rp, int t,
        const float* __restrict__ bias) {
    float *C, *Hout;
    if (layer == 0) { C = g_c0; Hout = g_h0[1 - rp]; }
    else            { C = g_c1; Hout = g_h1[1 - rp]; }
    int idx = blockIdx.x * 256 + threadIdx.x;
    int m = idx >> 9, j = idx & 511;
    float zi = bias[j], zf = bias[Hh + j];
    float zg = bias[2 * Hh + j], zo = bias[3 * Hh + j];
#pragma unroll
    for (int ksb = 0; ksb < 8; ksb++) {
        const float* zr = g_zpart + (ksb * 32 + m) * 2048;
        zi += zr[j];
        zf += zr[Hh + j];
        zg += zr[2 * Hh + j];
        zo += zr[3 * Hh + j];
    }
    float ig = 1.f / (1.f + expf(-zi));
    float fg = 1.f / (1.f + expf(-zf));
    float og = 1.f / (1.f + expf(-zo));
    float cn = fg * C[idx] + ig * tanhf(zg);
    float hn = og * tanhf(cn);
    C[idx] = cn;
    Hout[idx] = hn;
    if (layer == 1) {
        __nv_bfloat16 hi = __float2bfloat16(hn);
        size_t hrow = (size_t)t * Bb * Hh + idx;
        g_HallHi[hrow] = hi;
        g_HallLo[hrow] = __float2bfloat16(hn - __bfloat162float(hi));
    }
}

// ---------------- logits: mma.sync bf16 split GEMM (R12-proven) ----------
#define LROW 80
#define LOPSZ (128 * LROW)
#define LBUF  (4 * LOPSZ)

__global__ __launch_bounds__(256, 1) void logits_tc(const float* __restrict__ bd,
                                                    float* __restrict__ out) {
    extern __shared__ __align__(16) char lsm[];
    const int tid = threadIdx.x;
    const int wid = tid >> 5, lane = tid & 31;
    const int colbase = blockIdx.x * 128;
    const int rowbase = blockIdx.y * 128;
    const int wm = wid >> 2, wn = wid & 3;

    const unsigned smbase = smem_u32(lsm);

    const int sr = tid >> 1, part = tid & 1;
    const uint4* gAH = (const uint4*)(g_HallHi + (size_t)(rowbase + sr) * Hh) + part * 2;
    const uint4* gAL = (const uint4*)(g_HallLo + (size_t)(rowbase + sr) * Hh) + part * 2;
    const uint4* gBH = (const uint4*)(g_WdtHi + (size_t)(colbase + sr) * Hh) + part * 2;
    const uint4* gBL = (const uint4*)(g_WdtLo + (size_t)(colbase + sr) * Hh) + part * 2;
    const unsigned sdst = sr * LROW + part * 32;

    float d[4][4][4];
#pragma unroll
    for (int mi = 0; mi < 4; mi++)
#pragma unroll
        for (int ni = 0; ni < 4; ni++)
#pragma unroll
            for (int q = 0; q < 4; q++) d[mi][ni][q] = 0.f;

    const unsigned aoff = (lane & 15) * LROW + (lane >> 4) * 16;
    const unsigned boff = ((lane & 7) + ((lane >> 4) << 3)) * LROW
                        + (((lane >> 3) & 1) << 4);

    uint4 rAH0 = gAH[0], rAH1 = gAH[1];
    uint4 rAL0 = gAL[0], rAL1 = gAL[1];
    uint4 rBH0 = gBH[0], rBH1 = gBH[1];
    uint4 rBL0 = gBL[0], rBL1 = gBL[1];
    {
        char* bb = lsm + sdst;
        *(uint4*)(bb + 0 * LOPSZ)      = rAH0; *(uint4*)(bb + 0 * LOPSZ + 16) = rAH1;
        *(uint4*)(bb + 1 * LOPSZ)      = rAL0; *(uint4*)(bb + 1 * LOPSZ + 16) = rAL1;
        *(uint4*)(bb + 2 * LOPSZ)      = rBH0; *(uint4*)(bb + 2 * LOPSZ + 16) = rBH1;
        *(uint4*)(bb + 3 * LOPSZ)      = rBL0; *(uint4*)(bb + 3 * LOPSZ + 16) = rBL1;
    }
    __syncthreads();

    for (int c = 0; c < 16; c++) {
        const int p = c & 1;
        if (c < 15) {
            int o = (c + 1) * 4;
            rAH0 = gAH[o]; rAH1 = gAH[o + 1];
            rAL0 = gAL[o]; rAL1 = gAL[o + 1];
            rBH0 = gBH[o]; rBH1 = gBH[o + 1];
            rBL0 = gBL[o]; rBL1 = gBL[o + 1];
        }

        const unsigned bAH = smbase + p * LBUF + 0 * LOPSZ;
        const unsigned bAL = smbase + p * LBUF + 1 * LOPSZ;
        const unsigned bBH = smbase + p * LBUF + 2 * LOPSZ;
        const unsigned bBL = smbase + p * LBUF + 3 * LOPSZ;

#pragma unroll
        for (int ks = 0; ks < 2; ks++) {
            unsigned aHi[4][4], aLo[4][4], bHi[4][2], bLo[4][2];
#pragma unroll
            for (int mi = 0; mi < 4; mi++) {
                unsigned r = (wm * 64 + mi * 16) * LROW + ks * 32;
                ldsm4(aHi[mi], bAH + r + aoff);
                ldsm4(aLo[mi], bAL + r + aoff);
            }
#pragma unroll
            for (int nh = 0; nh < 2; nh++) {
                unsigned r = (wn * 32 + nh * 16) * LROW + ks * 32;
                unsigned t4[4];
                ldsm4(t4, bBH + r + boff);
                bHi[nh * 2][0] = t4[0]; bHi[nh * 2][1] = t4[1];
                bHi[nh * 2 + 1][0] = t4[2]; bHi[nh * 2 + 1][1] = t4[3];
                ldsm4(t4, bBL + r + boff);
                bLo[nh * 2][0] = t4[0]; bLo[nh * 2][1] = t4[1];
                bLo[nh * 2 + 1][0] = t4[2]; bLo[nh * 2 + 1][1] = t4[3];
            }
#pragma unroll
            for (int mi = 0; mi < 4; mi++)
#pragma unroll
                for (int ni = 0; ni < 4; ni++) {
                    mma16816(d[mi][ni], aHi[mi], bHi[ni]);
                    mma16816(d[mi][ni], aHi[mi], bLo[ni]);
                    mma16816(d[mi][ni], aLo[mi], bHi[ni]);
                }
        }

        if (c < 15) {
            char* bb = lsm + ((c + 1) & 1) * LBUF + sdst;
            *(uint4*)(bb + 0 * LOPSZ)      = rAH0; *(uint4*)(bb + 0 * LOPSZ + 16) = rAH1;
            *(uint4*)(bb + 1 * LOPSZ)      = rAL0; *(uint4*)(bb + 1 * LOPSZ + 16) = rAL1;
            *(uint4*)(bb + 2 * LOPSZ)      = rBH0; *(uint4*)(bb + 2 * LOPSZ + 16) = rBH1;
            *(uint4*)(bb + 3 * LOPSZ)      = rBL0; *(uint4*)(bb + 3 * LOPSZ + 16) = rBL1;
            __syncthreads();
        }
    }

    const int g = lane >> 2, tg = lane & 3;
#pragma unroll
    for (int mi = 0; mi < 4; mi++) {
#pragma unroll
        for (int half = 0; half < 2; half++) {
            int r = rowbase + wm * 64 + mi * 16 + g + half * 8;
            int orow = (r & 31) * Tt + (r >> 5);
            float* op = out + (size_t)orow * DVv;
#pragma unroll
            for (int ni = 0; ni < 4; ni++) {
                int col = colbase + wn * 32 + ni * 8 + tg * 2;
                float2 bj = *(const float2*)(bd + col);
                float2 v;
                v.x = d[mi][ni][half * 2 + 0] + bj.x;
                v.y = d[mi][ni][half * 2 + 1] + bj.y;
                *(float2*)(op + col) = v;
            }
        }
    }
}

// ---------------- launch ----------------
extern "C" void kernel_launch(void* const* d_in, const int* in_sizes, int n_in,
                              void* d_out, int out_size) {
    const float* initial_input  = (const float*)d_in[0];
    const float* hidden0        = (const float*)d_in[1];
    const float* cell0          = (const float*)d_in[2];
    const float* encoder_output = (const float*)d_in[3];
    const float* W1 = (const float*)d_in[4];
    const float* b1 = (const float*)d_in[5];
    const float* W2 = (const float*)d_in[6];
    const float* b2 = (const float*)d_in[7];
    const float* V  = (const float*)d_in[8];
    const float* bV = (const float*)d_in[9];
    const float* Wx0 = (const float*)d_in[10];
    const float* Wh0 = (const float*)d_in[11];
    const float* bL0 = (const float*)d_in[12];
    const float* Wx1 = (const float*)d_in[13];
    const float* Wh1 = (const float*)d_in[14];
    const float* bL1 = (const float*)d_in[15];
    const float* Wd  = (const float*)d_in[16];
    const float* bd  = (const float*)d_in[17];
    float* out = (float*)d_out;

    cudaFuncSetAttribute(logits_tc, cudaFuncAttributeMaxDynamicSharedMemorySize,
                         2 * LBUF);

    init_state<<<(Bb * Hh + 255) / 256, 256>>>(hidden0, cell0);

    repack_w<0><<<(64 * 8 * 160 * 16) / 256, 256>>>(Wx0, Wh0);
    repack_w<1><<<(64 * 8 * 128 * 16) / 256, 256>>>(Wx1, Wh1);
    transpose_wd<<<dim3(DVv / 32, Hh / 32), 256>>>(Wd);

    sgemm_enc<<<dim3(Aa / 64, (Bb * Ss) / 64), 256>>>(encoder_output, W2, b2);

    for (int t = 0; t < Tt; t++) {
        int rp = t & 1;
        // fused: layer-1 gates of step t-1 (per-batch) + attention of step t
        attention_step<<<Bb, 512>>>(encoder_output, W1, b1, V, bV,
                                    initial_input, bL1, rp, t, t > 0);
        lstm_mm<0><<<dim3(64, 8), 256>>>(rp);
        lstm_gates<<<64, 256>>>(0, rp, t, bL0);
        lstm_mm<1><<<dim3(64, 8), 256>>>(rp);
    }
    // final layer-1 gates (t = 63)
    lstm_gates<<<64, 256>>>(1, (Tt - 1) & 1, Tt - 1, bL1);

    logits_tc<<<dim3(DVv / 128, (Tt * Bb) / 128), 256, 2 * LBUF>>>(bd, out);

    long long total = (long long)Bb * Tt * DVv;
    if ((long long)out_size >= total + 4LL * Bb * Hh)
        write_tail<<<(Bb * Hh + 255) / 256, 256>>>(out + total);
}

// round 16
// speedup vs baseline: 1.8795x; 1.0494x over previous
#include <cuda_runtime.h>
#include <cuda_bf16.h>
#include <math.h>

typedef unsigned long long ull;

#define Bb 32
#define Tt 64
#define Ss 64
#define Ee 256
#define Hh 512
#define Aa 512
#define DVv 32000

// ---------------- device scratch (no allocation allowed) ----------------
__device__ float g_encproj[Bb * Ss * Aa];        // 4 MB
__device__ float g_h0[2][Bb * Hh];
__device__ float g_h1[2][Bb * Hh];
__device__ float g_c0[Bb * Hh];
__device__ float g_c1[Bb * Hh];
__device__ float g_x0[Bb * (Hh + Ee)];
__device__ float g_zpart[8 * Bb * 4 * Hh];       // 2 MB split-K partials
__device__ float g_qp[2][Bb][Aa];                // q partials (two h1-halves)
__device__ float g_sc[Bb * Ss];                  // attention scores
// repacked LSTM weights: per (bx, ksb) tile, [k2][np][2] ull pairs
__device__ ull g_wpk0[64 * 8 * 160 * 16];        // 10.5 MB (K=1280)
__device__ ull g_wpk1[64 * 8 * 128 * 16];        // 8.4 MB  (K=1024)
// logits tensor-core operands (bf16 2-term split); h1 history stored here
__device__ __nv_bfloat16 g_HallHi[Tt * Bb * Hh]; // 2 MB
__device__ __nv_bfloat16 g_HallLo[Tt * Bb * Hh]; // 2 MB
__device__ __nv_bfloat16 g_WdtHi[(size_t)DVv * Hh]; // 32.8 MB, [n][k]
__device__ __nv_bfloat16 g_WdtLo[(size_t)DVv * Hh]; // 32.8 MB

// ---------------- packed fp32x2 helpers (Blackwell FFMA2) ----------------
__device__ __forceinline__ void ffma2(ull &c, ull a, ull b) {
    asm("fma.rn.f32x2 %0, %1, %2, %0;" : "+l"(c) : "l"(a), "l"(b));
}
__device__ __forceinline__ ull pack2(float x, float y) {
    ull r; asm("mov.b64 %0, {%1, %2};" : "=l"(r) : "f"(x), "f"(y)); return r;
}
__device__ __forceinline__ float2 unpack2(ull v) {
    float2 f; asm("mov.b64 {%0, %1}, %2;" : "=f"(f.x), "=f"(f.y) : "l"(v)); return f;
}
__device__ __forceinline__ float tanh_fast(float x) {
    float y; asm("tanh.approx.f32 %0, %1;" : "=f"(y) : "f"(x)); return y;
}
__device__ __forceinline__ unsigned smem_u32(const void* p) {
    unsigned a;
    asm("{ .reg .u64 t; cvta.to.shared.u64 t, %1; cvt.u32.u64 %0, t; }"
        : "=r"(a) : "l"(p));
    return a;
}

// ---------------- mma.sync helpers (arch-neutral tensor core path) ----------
__device__ __forceinline__ void ldsm4(unsigned* r, unsigned addr) {
    asm volatile("ldmatrix.sync.aligned.m8n8.x4.shared.b16 {%0,%1,%2,%3}, [%4];"
                 : "=r"(r[0]), "=r"(r[1]), "=r"(r[2]), "=r"(r[3]) : "r"(addr));
}
__device__ __forceinline__ void mma16816(float* d, const unsigned* a,
                                         const unsigned* b) {
    asm volatile(
        "mma.sync.aligned.m16n8k16.row.col.f32.bf16.bf16.f32 "
        "{%0,%1,%2,%3}, {%4,%5,%6,%7}, {%8,%9}, {%0,%1,%2,%3};"
        : "+f"(d[0]), "+f"(d[1]), "+f"(d[2]), "+f"(d[3])
        : "r"(a[0]), "r"(a[1]), "r"(a[2]), "r"(a[3]), "r"(b[0]), "r"(b[1]));
}

// ---------------- init / tail ----------------
__global__ void init_state(const float* __restrict__ hidden0,
                           const float* __restrict__ cell0) {
    int i = blockIdx.x * 256 + threadIdx.x;
    if (i < Bb * Hh) {
        g_h0[0][i] = hidden0[i];
        g_h1[0][i] = hidden0[Bb * Hh + i];
        g_c0[i]    = cell0[i];
        g_c1[i]    = cell0[Bb * Hh + i];
    }
}

__global__ void write_tail(float* __restrict__ out) {
    int i = blockIdx.x * 256 + threadIdx.x;
    const int fin = (Tt & 1);  // T=64 -> final h lives in buffer 0
    if (i < Bb * Hh) {
        out[i]               = g_h0[fin][i];
        out[Bb * Hh + i]     = g_h1[fin][i];
        out[2 * Bb * Hh + i] = g_c0[i];
        out[3 * Bb * Hh + i] = g_c1[i];
    }
}

// ---------------- weight repack: [Wx;Wh] -> tile-contiguous pair layout ----
template<int LAYER>
__global__ __launch_bounds__(256) void repack_w(const float* __restrict__ Wx,
                                                const float* __restrict__ Wh) {
    constexpr int KX = LAYER ? Hh : (Hh + Ee);
    constexpr int CH = (KX + Hh) / 8;
    ull* dst = LAYER ? g_wpk1 : g_wpk0;
    int i = blockIdx.x * 256 + threadIdx.x;
    int tile = i / (CH * 16);
    int ti   = i % (CH * 16);
    int bx = tile >> 3, ksb = tile & 7;
    int k2 = ti >> 5;
    int np = (ti & 31) >> 1, j = ti & 1;
    int kg = ksb * CH + 2 * k2 + j;
    int colp = bx * 16 + np;
    const ull* src = (kg < KX)
        ? (const ull*)Wx + (size_t)kg * 1024 + colp
        : (const ull*)Wh + (size_t)(kg - KX) * 1024 + colp;
    dst[i] = *src;
}

// ---------------- Wd transpose + bf16 split (one-time) ----------------
__global__ __launch_bounds__(256) void transpose_wd(const float* __restrict__ Wd) {
    __shared__ float ts[32][33];
    int n0 = blockIdx.x * 32, k0 = blockIdx.y * 32;
    int c = threadIdx.x & 31, r8 = threadIdx.x >> 5;
#pragma unroll
    for (int p = 0; p < 4; p++) {
        int k = k0 + r8 + p * 8;
        ts[r8 + p * 8][c] = Wd[(size_t)k * DVv + n0 + c];
    }
    __syncthreads();
#pragma unroll
    for (int p = 0; p < 4; p++) {
        int n = n0 + r8 + p * 8;
        float v = ts[c][r8 + p * 8];
        __nv_bfloat16 hi = __float2bfloat16(v);
        float rem = v - __bfloat162float(hi);
        g_WdtHi[(size_t)n * Hh + k0 + c] = hi;
        g_WdtLo[(size_t)n * Hh + k0 + c] = __float2bfloat16(rem);
    }
}

// ---------------- enc-proj fp32 SGEMM (R7-proven) ----------------
__global__ __launch_bounds__(256) void sgemm_enc(const float* __restrict__ Am,
                                                 const float* __restrict__ Bm,
                                                 const float* __restrict__ bias) {
    constexpr int K = 512, N = Aa;
    float* Cm = g_encproj;

    __shared__ __align__(16) float As[16][64];
    __shared__ __align__(16) float Bs[16][64];

    const int tid = threadIdx.x;
    const int rowbase = blockIdx.y * 64;
    const int colbase = blockIdx.x * 64;

    const int lr  = tid >> 2;
    const int lkq = tid & 3;
    const int lk  = tid >> 4;
    const int lnq = tid & 15;
    const float* Ap = Am + (size_t)(rowbase + lr) * K + lkq * 4;
    const float* Bp = Bm + (size_t)lk * N + colbase + lnq * 4;

    const int mt = tid >> 4, nt = tid & 15;
    const int m0 = mt * 4, n0 = nt * 4;

    ull acc[2][4];
#pragma unroll
    for (int i = 0; i < 2; i++)
#pragma unroll
        for (int j = 0; j < 4; j++) acc[i][j] = 0ull;

    for (int kb = 0; kb < K; kb += 16) {
        float4 av = *(const float4*)(Ap + kb);
        float4 bv = *(const float4*)(Bp + (size_t)kb * N);
        __syncthreads();
        As[lkq * 4 + 0][lr] = av.x;
        As[lkq * 4 + 1][lr] = av.y;
        As[lkq * 4 + 2][lr] = av.z;
        As[lkq * 4 + 3][lr] = av.w;
        *(float4*)&Bs[lk][lnq * 4] = bv;
        __syncthreads();
#pragma unroll
        for (int k = 0; k < 16; k++) {
            ulonglong2 ap = *(const ulonglong2*)&As[k][m0];
            float4 b = *(const float4*)&Bs[k][n0];
            ull b0 = pack2(b.x, b.x), b1p = pack2(b.y, b.y);
            ull b2p = pack2(b.z, b.z), b3p = pack2(b.w, b.w);
            ffma2(acc[0][0], ap.x, b0);  ffma2(acc[1][0], ap.y, b0);
            ffma2(acc[0][1], ap.x, b1p); ffma2(acc[1][1], ap.y, b1p);
            ffma2(acc[0][2], ap.x, b2p); ffma2(acc[1][2], ap.y, b2p);
            ffma2(acc[0][3], ap.x, b3p); ffma2(acc[1][3], ap.y, b3p);
        }
    }

#pragma unroll
    for (int j = 0; j < 4; j++) {
        int col = colbase + n0 + j;
        float bj = bias[col];
        float2 v0 = unpack2(acc[0][j]);
        float2 v1 = unpack2(acc[1][j]);
        float vals[4] = {v0.x, v0.y, v1.x, v1.y};
#pragma unroll
        for (int i = 0; i < 4; i++) {
            int r = rowbase + m0 + i;
            Cm[(size_t)r * N + col] = vals[i] + bj;
        }
    }
}

// ---------------- K1: layer-1 gates of t-1 (half-batch) + q partial ----------
// 64 blocks: block = (b, half). Prologue finishes gates for its 256 units of
// batch b (fixed ksb reduce order -> bit-identical), updates c1/h1, writes the
// bf16 h1-history, keeps its h1-half in smem, and computes the q-GEMM partial
// q_p[half] = h1_half @ W1[half rows]. No cross-block h1 dependency.
__global__ __launch_bounds__(256) void gates_q(
    const float* __restrict__ W1, const float* __restrict__ bL1,
    int rp, int t, int dopro) {
    const int b = blockIdx.x >> 1, half = blockIdx.x & 1;
    const int tid = threadIdx.x;
    const int j = half * 256 + tid;
    __shared__ float h1s[256];
    __shared__ float qred[2][Aa];

    float hn;
    if (dopro) {
        float zi = bL1[j], zf = bL1[Hh + j];
        float zg = bL1[2 * Hh + j], zo = bL1[3 * Hh + j];
#pragma unroll
        for (int ksb = 0; ksb < 8; ksb++) {
            const float* zr = g_zpart + (ksb * 32 + b) * 2048;
            zi += zr[j];
            zf += zr[Hh + j];
            zg += zr[2 * Hh + j];
            zo += zr[3 * Hh + j];
        }
        float ig = 1.f / (1.f + expf(-zi));
        float fg = 1.f / (1.f + expf(-zf));
        float og = 1.f / (1.f + expf(-zo));
        int idx = b * Hh + j;
        float cn = fg * g_c1[idx] + ig * tanhf(zg);
        hn = og * tanhf(cn);
        g_c1[idx] = cn;
        g_h1[rp][idx] = hn;
        __nv_bfloat16 hi = __float2bfloat16(hn);
        size_t hrow = ((size_t)(t - 1) * Bb + b) * Hh + j;
        g_HallHi[hrow] = hi;
        g_HallLo[hrow] = __float2bfloat16(hn - __bfloat162float(hi));
    } else {
        hn = g_h1[rp][b * Hh + j];
    }
    h1s[tid] = hn;
    __syncthreads();

    // q partial over W1 rows [half*256, +256): 2 k-slices x (4 cols/thread)
    const int ks = tid >> 7, cg = tid & 127;
    const int c4 = cg * 4;
    const float* wb = W1 + (size_t)(half * 256 + ks * 128) * Aa + c4;
    const float* hsl = h1s + ks * 128;
    float a0 = 0.f, a1 = 0.f, a2 = 0.f, a3 = 0.f;
#pragma unroll 4
    for (int k = 0; k < 128; k++) {
        float hv = hsl[k];
        float4 w = *(const float4*)(wb + (size_t)k * Aa);
        a0 += hv * w.x; a1 += hv * w.y; a2 += hv * w.z; a3 += hv * w.w;
    }
    qred[ks][c4]     = a0; qred[ks][c4 + 1] = a1;
    qred[ks][c4 + 2] = a2; qred[ks][c4 + 3] = a3;
    __syncthreads();
    g_qp[half][b][tid]       = qred[0][tid] + qred[1][tid];
    g_qp[half][b][tid + 256] = qred[0][tid + 256] + qred[1][tid + 256];
}

// ---------------- K2: scores (128 blocks, 16 s-values each) ----------------
__global__ __launch_bounds__(256) void attn_scores(
    const float* __restrict__ b1, const float* __restrict__ V,
    const float* __restrict__ bV) {
    const int b = blockIdx.x, sg = blockIdx.y;
    const int tid = threadIdx.x, warp = tid >> 5, lane = tid & 31;
    __shared__ float qs[Aa], Vs[Aa];
    qs[tid]       = g_qp[0][b][tid] + g_qp[1][b][tid] + b1[tid];
    qs[tid + 256] = g_qp[0][b][tid + 256] + g_qp[1][b][tid + 256] + b1[tid + 256];
    Vs[tid] = V[tid];
    Vs[tid + 256] = V[tid + 256];
    __syncthreads();

    const float* ep = g_encproj + (size_t)b * Ss * Aa;
#pragma unroll
    for (int r = 0; r < 2; r++) {
        int s = sg * 16 + warp * 2 + r;
        const float* eps = ep + s * Aa;
        float p = 0.f;
#pragma unroll 4
        for (int a = lane; a < Aa; a += 32)
            p += tanh_fast(eps[a] + qs[a]) * Vs[a];
#pragma unroll
        for (int o = 16; o; o >>= 1) p += __shfl_xor_sync(0xffffffffu, p, o);
        if (lane == 0) g_sc[b * Ss + s] = p + bV[0];
    }
}

// ---------------- K3: softmax + context halves + token concat ----------------
__global__ __launch_bounds__(256) void attn_ctx(
    const float* __restrict__ enc, const float* __restrict__ tokens, int t) {
    const int b = blockIdx.x, y = blockIdx.y;
    const int tid = threadIdx.x, warp = tid >> 5, lane = tid & 31;
    __shared__ float at[Ss];

    if (warp == 0) {   // softmax over S=64 (redundant per half-block, cheap)
        float s0 = g_sc[b * Ss + lane], s1 = g_sc[b * Ss + 32 + lane];
        float mx = fmaxf(s0, s1);
#pragma unroll
        for (int o = 16; o; o >>= 1) mx = fmaxf(mx, __shfl_xor_sync(0xffffffffu, mx, o));
        float e0 = expf(s0 - mx), e1 = expf(s1 - mx);
        float sm = e0 + e1;
#pragma unroll
        for (int o = 16; o; o >>= 1) sm += __shfl_xor_sync(0xffffffffu, sm, o);
        float inv = 1.f / sm;
        at[lane] = e0 * inv;
        at[lane + 32] = e1 * inv;
    }
    __syncthreads();

    const float* eb = enc + (size_t)b * Ss * Hh + y * 256;
    float c = 0.f;
#pragma unroll 8
    for (int s = 0; s < Ss; s++) c += at[s] * eb[s * Hh + tid];
    float* x0 = g_x0 + b * (Hh + Ee);
    x0[y * 256 + tid] = c;
    if (y == 1) x0[Hh + tid] = tokens[((size_t)b * Tt + t) * Ee + tid];
}

// ---------------- LSTM matmul: split-K, repacked weights (R7-proven) ---------
template<int LAYER>
__global__ __launch_bounds__(256) void lstm_mm(int rp) {
    constexpr int KX  = LAYER ? Hh : (Hh + Ee);   // 512 or 768
    constexpr int CH  = (KX + Hh) / 8;            // 128 or 160
    constexpr int C2  = CH / 2;
    constexpr int STR = CH + 2;
    const float* X     = LAYER ? g_h0[1 - rp] : g_x0;
    const float* Hprev = LAYER ? g_h1[rp]     : g_h0[rp];
    const ull* wpk     = LAYER ? g_wpk1       : g_wpk0;

    __shared__ __align__(16) ull xd[32 * STR];

    const int tid = threadIdx.x;
    const int ksb = blockIdx.y;
    const int k0  = ksb * CH;
    const int bx  = blockIdx.x;
    const int c0  = bx * 32;

    {
        int m = tid >> 3;
        int part = tid & 7;
        constexpr int PER = CH / 8;
        int kb = part * PER;
        const float* xrow = X + (size_t)m * KX;
        const float* hrow = Hprev + m * Hh;
        ull* dst = xd + m * STR + kb;
#pragma unroll
        for (int q = 0; q < PER; q += 4) {
            int kg = k0 + kb + q;
            float4 v = (kg < KX) ? *(const float4*)(xrow + kg)
                                 : *(const float4*)(hrow + (kg - KX));
            dst[q + 0] = pack2(v.x, v.x);
            dst[q + 1] = pack2(v.y, v.y);
            dst[q + 2] = pack2(v.z, v.z);
            dst[q + 3] = pack2(v.w, v.w);
        }
    }
    __syncthreads();

    const int np = tid & 15;
    const int ms = tid >> 4;

    const ulonglong2* wp = (const ulonglong2*)(wpk + (size_t)(bx * 8 + ksb) * (CH * 16)) + np;
    const ulonglong2* xap = (const ulonglong2*)(xd + ms * STR);
    const ulonglong2* xbp = (const ulonglong2*)(xd + (ms + 16) * STR);

    ull acc0 = 0ull, acc1 = 0ull;
#pragma unroll 8
    for (int k2 = 0; k2 < C2; k2++) {
        ulonglong2 w = wp[k2 * 16];
        ulonglong2 a = xap[k2];
        ulonglong2 b = xbp[k2];
        ffma2(acc0, a.x, w.x);
        ffma2(acc1, b.x, w.x);
        ffma2(acc0, a.y, w.y);
        ffma2(acc1, b.y, w.y);
    }

    *(ull*)&g_zpart[((ksb * 32 + ms) * 2048) + c0 + 2 * np]      = acc0;
    *(ull*)&g_zpart[((ksb * 32 + ms + 16) * 2048) + c0 + 2 * np] = acc1;
}

// ---------------- gate epilogue (layer 0 every step; layer 1 only final) -----
__global__ __launch_bounds__(256) void lstm_gates(int layer, int rp, int t,
        const float* __restrict__ bias) {
    float *C, *Hout;
    if (layer == 0) { C = g_c0; Hout = g_h0[1 - rp]; }
    else            { C = g_c1; Hout = g_h1[1 - rp]; }
    int idx = blockIdx.x * 256 + threadIdx.x;
    int m = idx >> 9, j = idx & 511;
    float zi = bias[j], zf = bias[Hh + j];
    float zg = bias[2 * Hh + j], zo = bias[3 * Hh + j];
#pragma unroll
    for (int ksb = 0; ksb < 8; ksb++) {
        const float* zr = g_zpart + (ksb * 32 + m) * 2048;
        zi += zr[j];
        zf += zr[Hh + j];
        zg += zr[2 * Hh + j];
        zo += zr[3 * Hh + j];
    }
    float ig = 1.f / (1.f + expf(-zi));
    float fg = 1.f / (1.f + expf(-zf));
    float og = 1.f / (1.f + expf(-zo));
    float cn = fg * C[idx] + ig * tanhf(zg);
    float hn = og * tanhf(cn);
    C[idx] = cn;
    Hout[idx] = hn;
    if (layer == 1) {
        __nv_bfloat16 hi = __float2bfloat16(hn);
        size_t hrow = (size_t)t * Bb * Hh + idx;
        g_HallHi[hrow] = hi;
        g_HallLo[hrow] = __float2bfloat16(hn - __bfloat162float(hi));
    }
}

// ---------------- logits: mma.sync bf16 split GEMM (R12-proven) ----------
#define LROW 80
#define LOPSZ (128 * LROW)
#define LBUF  (4 * LOPSZ)

__global__ __launch_bounds__(256, 1) void logits_tc(const float* __restrict__ bd,
                                                    float* __restrict__ out) {
    extern __shared__ __align__(16) char lsm[];
    const int tid = threadIdx.x;
    const int wid = tid >> 5, lane = tid & 31;
    const int colbase = blockIdx.x * 128;
    const int rowbase = blockIdx.y * 128;
    const int wm = wid >> 2, wn = wid & 3;

    const unsigned smbase = smem_u32(lsm);

    const int sr = tid >> 1, part = tid & 1;
    const uint4* gAH = (const uint4*)(g_HallHi + (size_t)(rowbase + sr) * Hh) + part * 2;
    const uint4* gAL = (const uint4*)(g_HallLo + (size_t)(rowbase + sr) * Hh) + part * 2;
    const uint4* gBH = (const uint4*)(g_WdtHi + (size_t)(colbase + sr) * Hh) + part * 2;
    const uint4* gBL = (const uint4*)(g_WdtLo + (size_t)(colbase + sr) * Hh) + part * 2;
    const unsigned sdst = sr * LROW + part * 32;

    float d[4][4][4];
#pragma unroll
    for (int mi = 0; mi < 4; mi++)
#pragma unroll
        for (int ni = 0; ni < 4; ni++)
#pragma unroll
            for (int q = 0; q < 4; q++) d[mi][ni][q] = 0.f;

    const unsigned aoff = (lane & 15) * LROW + (lane >> 4) * 16;
    const unsigned boff = ((lane & 7) + ((lane >> 4) << 3)) * LROW
                        + (((lane >> 3) & 1) << 4);

    uint4 rAH0 = gAH[0], rAH1 = gAH[1];
    uint4 rAL0 = gAL[0], rAL1 = gAL[1];
    uint4 rBH0 = gBH[0], rBH1 = gBH[1];
    uint4 rBL0 = gBL[0], rBL1 = gBL[1];
    {
        char* bb = lsm + sdst;
        *(uint4*)(bb + 0 * LOPSZ)      = rAH0; *(uint4*)(bb + 0 * LOPSZ + 16) = rAH1;
        *(uint4*)(bb + 1 * LOPSZ)      = rAL0; *(uint4*)(bb + 1 * LOPSZ + 16) = rAL1;
        *(uint4*)(bb + 2 * LOPSZ)      = rBH0; *(uint4*)(bb + 2 * LOPSZ + 16) = rBH1;
        *(uint4*)(bb + 3 * LOPSZ)      = rBL0; *(uint4*)(bb + 3 * LOPSZ + 16) = rBL1;
    }
    __syncthreads();

    for (int c = 0; c < 16; c++) {
        const int p = c & 1;
        if (c < 15) {
            int o = (c + 1) * 4;
            rAH0 = gAH[o]; rAH1 = gAH[o + 1];
            rAL0 = gAL[o]; rAL1 = gAL[o + 1];
            rBH0 = gBH[o]; rBH1 = gBH[o + 1];
            rBL0 = gBL[o]; rBL1 = gBL[o + 1];
        }

        const unsigned bAH = smbase + p * LBUF + 0 * LOPSZ;
        const unsigned bAL = smbase + p * LBUF + 1 * LOPSZ;
        const unsigned bBH = smbase + p * LBUF + 2 * LOPSZ;
        const unsigned bBL = smbase + p * LBUF + 3 * LOPSZ;

#pragma unroll
        for (int ks = 0; ks < 2; ks++) {
            unsigned aHi[4][4], aLo[4][4], bHi[4][2], bLo[4][2];
#pragma unroll
            for (int mi = 0; mi < 4; mi++) {
                unsigned r = (wm * 64 + mi * 16) * LROW + ks * 32;
                ldsm4(aHi[mi], bAH + r + aoff);
                ldsm4(aLo[mi], bAL + r + aoff);
            }
#pragma unroll
            for (int nh = 0; nh < 2; nh++) {
                unsigned r = (wn * 32 + nh * 16) * LROW + ks * 32;
                unsigned t4[4];
                ldsm4(t4, bBH + r + boff);
                bHi[nh * 2][0] = t4[0]; bHi[nh * 2][1] = t4[1];
                bHi[nh * 2 + 1][0] = t4[2]; bHi[nh * 2 + 1][1] = t4[3];
                ldsm4(t4, bBL + r + boff);
                bLo[nh * 2][0] = t4[0]; bLo[nh * 2][1] = t4[1];
                bLo[nh * 2 + 1][0] = t4[2]; bLo[nh * 2 + 1][1] = t4[3];
            }
#pragma unroll
            for (int mi = 0; mi < 4; mi++)
#pragma unroll
                for (int ni = 0; ni < 4; ni++) {
                    mma16816(d[mi][ni], aHi[mi], bHi[ni]);
                    mma16816(d[mi][ni], aHi[mi], bLo[ni]);
                    mma16816(d[mi][ni], aLo[mi], bHi[ni]);
                }
        }

        if (c < 15) {
            char* bb = lsm + ((c + 1) & 1) * LBUF + sdst;
            *(uint4*)(bb + 0 * LOPSZ)      = rAH0; *(uint4*)(bb + 0 * LOPSZ + 16) = rAH1;
            *(uint4*)(bb + 1 * LOPSZ)      = rAL0; *(uint4*)(bb + 1 * LOPSZ + 16) = rAL1;
            *(uint4*)(bb + 2 * LOPSZ)      = rBH0; *(uint4*)(bb + 2 * LOPSZ + 16) = rBH1;
            *(uint4*)(bb + 3 * LOPSZ)      = rBL0; *(uint4*)(bb + 3 * LOPSZ + 16) = rBL1;
            __syncthreads();
        }
    }

    const int g = lane >> 2, tg = lane & 3;
#pragma unroll
    for (int mi = 0; mi < 4; mi++) {
#pragma unroll
        for (int half = 0; half < 2; half++) {
            int r = rowbase + wm * 64 + mi * 16 + g + half * 8;
            int orow = (r & 31) * Tt + (r >> 5);
            float* op = out + (size_t)orow * DVv;
#pragma unroll
            for (int ni = 0; ni < 4; ni++) {
                int col = colbase + wn * 32 + ni * 8 + tg * 2;
                float2 bj = *(const float2*)(bd + col);
                float2 v;
                v.x = d[mi][ni][half * 2 + 0] + bj.x;
                v.y = d[mi][ni][half * 2 + 1] + bj.y;
                *(float2*)(op + col) = v;
            }
        }
    }
}

// ---------------- launch ----------------
extern "C" void kernel_launch(void* const* d_in, const int* in_sizes, int n_in,
                              void* d_out, int out_size) {
    const float* initial_input  = (const float*)d_in[0];
    const float* hidden0        = (const float*)d_in[1];
    const float* cell0          = (const float*)d_in[2];
    const float* encoder_output = (const float*)d_in[3];
    const float* W1 = (const float*)d_in[4];
    const float* b1 = (const float*)d_in[5];
    const float* W2 = (const float*)d_in[6];
    const float* b2 = (const float*)d_in[7];
    const float* V  = (const float*)d_in[8];
    const float* bV = (const float*)d_in[9];
    const float* Wx0 = (const float*)d_in[10];
    const float* Wh0 = (const float*)d_in[11];
    const float* bL0 = (const float*)d_in[12];
    const float* Wx1 = (const float*)d_in[13];
    const float* Wh1 = (const float*)d_in[14];
    const float* bL1 = (const float*)d_in[15];
    const float* Wd  = (const float*)d_in[16];
    const float* bd  = (const float*)d_in[17];
    float* out = (float*)d_out;

    cudaFuncSetAttribute(logits_tc, cudaFuncAttributeMaxDynamicSharedMemorySize,
                         2 * LBUF);

    init_state<<<(Bb * Hh + 255) / 256, 256>>>(hidden0, cell0);

    repack_w<0><<<(64 * 8 * 160 * 16) / 256, 256>>>(Wx0, Wh0);
    repack_w<1><<<(64 * 8 * 128 * 16) / 256, 256>>>(Wx1, Wh1);
    transpose_wd<<<dim3(DVv / 32, Hh / 32), 256>>>(Wd);

    sgemm_enc<<<dim3(Aa / 64, (Bb * Ss) / 64), 256>>>(encoder_output, W2, b2);

    for (int t = 0; t < Tt; t++) {
        int rp = t & 1;
        gates_q<<<2 * Bb, 256>>>(W1, bL1, rp, t, t > 0);
        attn_scores<<<dim3(Bb, 4), 256>>>(b1, V, bV);
        attn_ctx<<<dim3(Bb, 2), 256>>>(encoder_output, initial_input, t);
        lstm_mm<0><<<dim3(64, 8), 256>>>(rp);
        lstm_gates<<<64, 256>>>(0, rp, t, bL0);
        lstm_mm<1><<<dim3(64, 8), 256>>>(rp);
    }
    // final layer-1 gates (t = 63)
    lstm_gates<<<64, 256>>>(1, (Tt - 1) & 1, Tt - 1, bL1);

    logits_tc<<<dim3(DVv / 128, (Tt * Bb) / 128), 256, 2 * LBUF>>>(bd, out);

    long long total = (long long)Bb * Tt * DVv;
    if ((long long)out_size >= total + 4LL * Bb * Hh)
        write_tail<<<(Bb * Hh + 255) / 256, 256>>>(out + total);
}

// round 17
// speedup vs baseline: 1.9386x; 1.0315x over previous
#include <cuda_runtime.h>
#include <cuda_bf16.h>
#include <math.h>

typedef unsigned long long ull;

#define Bb 32
#define Tt 64
#define Ss 64
#define Ee 256
#define Hh 512
#define Aa 512
#define DVv 32000

// ---------------- device scratch (no allocation allowed) ----------------
__device__ float g_encproj[Bb * Ss * Aa];        // 4 MB
__device__ float g_h0[2][Bb * Hh];
__device__ float g_h1[2][Bb * Hh];
__device__ float g_c0[Bb * Hh];
__device__ float g_c1[Bb * Hh];
__device__ float g_x0[Bb * (Hh + Ee)];
__device__ float g_zpart[8 * Bb * 4 * Hh];       // 2 MB split-K partials
__device__ float g_qp[4][Bb][Aa];                // q partials (4 h1-quarters)
__device__ float g_sc[Bb * Ss];                  // attention scores
// repacked LSTM weights: per (bx, ksb) tile, [k2][np][2] ull pairs
__device__ ull g_wpk0[64 * 8 * 160 * 16];        // 10.5 MB (K=1280)
__device__ ull g_wpk1[64 * 8 * 128 * 16];        // 8.4 MB  (K=1024)
// logits tensor-core operands (bf16 2-term split); h1 history stored here
__device__ __nv_bfloat16 g_HallHi[Tt * Bb * Hh]; // 2 MB
__device__ __nv_bfloat16 g_HallLo[Tt * Bb * Hh]; // 2 MB
__device__ __nv_bfloat16 g_WdtHi[(size_t)DVv * Hh]; // 32.8 MB, [n][k]
__device__ __nv_bfloat16 g_WdtLo[(size_t)DVv * Hh]; // 32.8 MB

// ---------------- packed fp32x2 helpers (Blackwell FFMA2) ----------------
__device__ __forceinline__ void ffma2(ull &c, ull a, ull b) {
    asm("fma.rn.f32x2 %0, %1, %2, %0;" : "+l"(c) : "l"(a), "l"(b));
}
__device__ __forceinline__ ull pack2(float x, float y) {
    ull r; asm("mov.b64 %0, {%1, %2};" : "=l"(r) : "f"(x), "f"(y)); return r;
}
__device__ __forceinline__ float2 unpack2(ull v) {
    float2 f; asm("mov.b64 {%0, %1}, %2;" : "=f"(f.x), "=f"(f.y) : "l"(v)); return f;
}
__device__ __forceinline__ float tanh_fast(float x) {
    float y; asm("tanh.approx.f32 %0, %1;" : "=f"(y) : "f"(x)); return y;
}
__device__ __forceinline__ unsigned smem_u32(const void* p) {
    unsigned a;
    asm("{ .reg .u64 t; cvta.to.shared.u64 t, %1; cvt.u32.u64 %0, t; }"
        : "=r"(a) : "l"(p));
    return a;
}

// ---------------- mma.sync helpers (arch-neutral tensor core path) ----------
__device__ __forceinline__ void ldsm4(unsigned* r, unsigned addr) {
    asm volatile("ldmatrix.sync.aligned.m8n8.x4.shared.b16 {%0,%1,%2,%3}, [%4];"
                 : "=r"(r[0]), "=r"(r[1]), "=r"(r[2]), "=r"(r[3]) : "r"(addr));
}
__device__ __forceinline__ void mma16816(float* d, const unsigned* a,
                                         const unsigned* b) {
    asm volatile(
        "mma.sync.aligned.m16n8k16.row.col.f32.bf16.bf16.f32 "
        "{%0,%1,%2,%3}, {%4,%5,%6,%7}, {%8,%9}, {%0,%1,%2,%3};"
        : "+f"(d[0]), "+f"(d[1]), "+f"(d[2]), "+f"(d[3])
        : "r"(a[0]), "r"(a[1]), "r"(a[2]), "r"(a[3]), "r"(b[0]), "r"(b[1]));
}

// ---------------- init / tail ----------------
__global__ void init_state(const float* __restrict__ hidden0,
                           const float* __restrict__ cell0) {
    int i = blockIdx.x * 256 + threadIdx.x;
    if (i < Bb * Hh) {
        g_h0[0][i] = hidden0[i];
        g_h1[0][i] = hidden0[Bb * Hh + i];
        g_c0[i]    = cell0[i];
        g_c1[i]    = cell0[Bb * Hh + i];
    }
}

__global__ void write_tail(float* __restrict__ out) {
    int i = blockIdx.x * 256 + threadIdx.x;
    const int fin = (Tt & 1);  // T=64 -> final h lives in buffer 0
    if (i < Bb * Hh) {
        out[i]               = g_h0[fin][i];
        out[Bb * Hh + i]     = g_h1[fin][i];
        out[2 * Bb * Hh + i] = g_c0[i];
        out[3 * Bb * Hh + i] = g_c1[i];
    }
}

// ---------------- weight repack: [Wx;Wh] -> tile-contiguous pair layout ----
template<int LAYER>
__global__ __launch_bounds__(256) void repack_w(const float* __restrict__ Wx,
                                                const float* __restrict__ Wh) {
    constexpr int KX = LAYER ? Hh : (Hh + Ee);
    constexpr int CH = (KX + Hh) / 8;
    ull* dst = LAYER ? g_wpk1 : g_wpk0;
    int i = blockIdx.x * 256 + threadIdx.x;
    int tile = i / (CH * 16);
    int ti   = i % (CH * 16);
    int bx = tile >> 3, ksb = tile & 7;
    int k2 = ti >> 5;
    int np = (ti & 31) >> 1, j = ti & 1;
    int kg = ksb * CH + 2 * k2 + j;
    int colp = bx * 16 + np;
    const ull* src = (kg < KX)
        ? (const ull*)Wx + (size_t)kg * 1024 + colp
        : (const ull*)Wh + (size_t)(kg - KX) * 1024 + colp;
    dst[i] = *src;
}

// ---------------- Wd transpose + bf16 split (one-time) ----------------
__global__ __launch_bounds__(256) void transpose_wd(const float* __restrict__ Wd) {
    __shared__ float ts[32][33];
    int n0 = blockIdx.x * 32, k0 = blockIdx.y * 32;
    int c = threadIdx.x & 31, r8 = threadIdx.x >> 5;
#pragma unroll
    for (int p = 0; p < 4; p++) {
        int k = k0 + r8 + p * 8;
        ts[r8 + p * 8][c] = Wd[(size_t)k * DVv + n0 + c];
    }
    __syncthreads();
#pragma unroll
    for (int p = 0; p < 4; p++) {
        int n = n0 + r8 + p * 8;
        float v = ts[c][r8 + p * 8];
        __nv_bfloat16 hi = __float2bfloat16(v);
        float rem = v - __bfloat162float(hi);
        g_WdtHi[(size_t)n * Hh + k0 + c] = hi;
        g_WdtLo[(size_t)n * Hh + k0 + c] = __float2bfloat16(rem);
    }
}

// ---------------- enc-proj fp32 SGEMM (R7-proven) ----------------
__global__ __launch_bounds__(256) void sgemm_enc(const float* __restrict__ Am,
                                                 const float* __restrict__ Bm,
                                                 const float* __restrict__ bias) {
    constexpr int K = 512, N = Aa;
    float* Cm = g_encproj;

    __shared__ __align__(16) float As[16][64];
    __shared__ __align__(16) float Bs[16][64];

    const int tid = threadIdx.x;
    const int rowbase = blockIdx.y * 64;
    const int colbase = blockIdx.x * 64;

    const int lr  = tid >> 2;
    const int lkq = tid & 3;
    const int lk  = tid >> 4;
    const int lnq = tid & 15;
    const float* Ap = Am + (size_t)(rowbase + lr) * K + lkq * 4;
    const float* Bp = Bm + (size_t)lk * N + colbase + lnq * 4;

    const int mt = tid >> 4, nt = tid & 15;
    const int m0 = mt * 4, n0 = nt * 4;

    ull acc[2][4];
#pragma unroll
    for (int i = 0; i < 2; i++)
#pragma unroll
        for (int j = 0; j < 4; j++) acc[i][j] = 0ull;

    for (int kb = 0; kb < K; kb += 16) {
        float4 av = *(const float4*)(Ap + kb);
        float4 bv = *(const float4*)(Bp + (size_t)kb * N);
        __syncthreads();
        As[lkq * 4 + 0][lr] = av.x;
        As[lkq * 4 + 1][lr] = av.y;
        As[lkq * 4 + 2][lr] = av.z;
        As[lkq * 4 + 3][lr] = av.w;
        *(float4*)&Bs[lk][lnq * 4] = bv;
        __syncthreads();
#pragma unroll
        for (int k = 0; k < 16; k++) {
            ulonglong2 ap = *(const ulonglong2*)&As[k][m0];
            float4 b = *(const float4*)&Bs[k][n0];
            ull b0 = pack2(b.x, b.x), b1p = pack2(b.y, b.y);
            ull b2p = pack2(b.z, b.z), b3p = pack2(b.w, b.w);
            ffma2(acc[0][0], ap.x, b0);  ffma2(acc[1][0], ap.y, b0);
            ffma2(acc[0][1], ap.x, b1p); ffma2(acc[1][1], ap.y, b1p);
            ffma2(acc[0][2], ap.x, b2p); ffma2(acc[1][2], ap.y, b2p);
            ffma2(acc[0][3], ap.x, b3p); ffma2(acc[1][3], ap.y, b3p);
        }
    }

#pragma unroll
    for (int j = 0; j < 4; j++) {
        int col = colbase + n0 + j;
        float bj = bias[col];
        float2 v0 = unpack2(acc[0][j]);
        float2 v1 = unpack2(acc[1][j]);
        float vals[4] = {v0.x, v0.y, v1.x, v1.y};
#pragma unroll
        for (int i = 0; i < 4; i++) {
            int r = rowbase + m0 + i;
            Cm[(size_t)r * N + col] = vals[i] + bj;
        }
    }
}

// ---------------- K1: layer-1 gates of t-1 (quarter-batch) + q partial -------
// 128 blocks: block = (b, quar). Prologue finishes gates for its 128 units of
// batch b (fixed ksb reduce order), updates c1/h1, writes bf16 h1-history,
// keeps its h1-quarter in smem, computes q-partial over its 128 W1 rows.
__global__ __launch_bounds__(256) void gates_q(
    const float* __restrict__ W1, const float* __restrict__ bL1,
    int rp, int t, int dopro) {
    const int b = blockIdx.x >> 2, quar = blockIdx.x & 3;
    const int tid = threadIdx.x;
    __shared__ float h1s[128];
    __shared__ float qred[2][Aa];

    if (tid < 128) {
        const int j = quar * 128 + tid;
        float hn;
        if (dopro) {
            float zi = bL1[j], zf = bL1[Hh + j];
            float zg = bL1[2 * Hh + j], zo = bL1[3 * Hh + j];
#pragma unroll
            for (int ksb = 0; ksb < 8; ksb++) {
                const float* zr = g_zpart + (ksb * 32 + b) * 2048;
                zi += zr[j];
                zf += zr[Hh + j];
                zg += zr[2 * Hh + j];
                zo += zr[3 * Hh + j];
            }
            float ig = 1.f / (1.f + expf(-zi));
            float fg = 1.f / (1.f + expf(-zf));
            float og = 1.f / (1.f + expf(-zo));
            int idx = b * Hh + j;
            float cn = fg * g_c1[idx] + ig * tanhf(zg);
            hn = og * tanhf(cn);
            g_c1[idx] = cn;
            g_h1[rp][idx] = hn;
            __nv_bfloat16 hi = __float2bfloat16(hn);
            size_t hrow = ((size_t)(t - 1) * Bb + b) * Hh + j;
            g_HallHi[hrow] = hi;
            g_HallLo[hrow] = __float2bfloat16(hn - __bfloat162float(hi));
        } else {
            hn = g_h1[rp][b * Hh + j];
        }
        h1s[tid] = hn;
    }
    __syncthreads();

    // q partial over W1 rows [quar*128, +128): 2 k-slices of 64 x 4 cols/thread
    const int ks = tid >> 7, cg = tid & 127;
    const int c4 = cg * 4;
    const float* wb = W1 + (size_t)(quar * 128 + ks * 64) * Aa + c4;
    const float* hsl = h1s + ks * 64;
    float a0 = 0.f, a1 = 0.f, a2 = 0.f, a3 = 0.f;
#pragma unroll 8
    for (int k = 0; k < 64; k++) {
        float hv = hsl[k];
        float4 w = *(const float4*)(wb + (size_t)k * Aa);
        a0 += hv * w.x; a1 += hv * w.y; a2 += hv * w.z; a3 += hv * w.w;
    }
    qred[ks][c4]     = a0; qred[ks][c4 + 1] = a1;
    qred[ks][c4 + 2] = a2; qred[ks][c4 + 3] = a3;
    __syncthreads();
    g_qp[quar][b][tid]       = qred[0][tid] + qred[1][tid];
    g_qp[quar][b][tid + 256] = qred[0][tid + 256] + qred[1][tid + 256];
}

// ---------------- K2: scores (128 blocks, 16 s-values each) ----------------
__global__ __launch_bounds__(256) void attn_scores(
    const float* __restrict__ b1, const float* __restrict__ V,
    const float* __restrict__ bV) {
    const int b = blockIdx.x, sg = blockIdx.y;
    const int tid = threadIdx.x, warp = tid >> 5, lane = tid & 31;
    __shared__ float qs[Aa], Vs[Aa];
    qs[tid] = ((g_qp[0][b][tid] + g_qp[1][b][tid])
             + (g_qp[2][b][tid] + g_qp[3][b][tid])) + b1[tid];
    qs[tid + 256] = ((g_qp[0][b][tid + 256] + g_qp[1][b][tid + 256])
                   + (g_qp[2][b][tid + 256] + g_qp[3][b][tid + 256])) + b1[tid + 256];
    Vs[tid] = V[tid];
    Vs[tid + 256] = V[tid + 256];
    __syncthreads();

    const float* ep = g_encproj + (size_t)b * Ss * Aa;
#pragma unroll
    for (int r = 0; r < 2; r++) {
        int s = sg * 16 + warp * 2 + r;
        const float* eps = ep + s * Aa;
        float p = 0.f;
#pragma unroll 4
        for (int a = lane; a < Aa; a += 32)
            p += tanh_fast(eps[a] + qs[a]) * Vs[a];
#pragma unroll
        for (int o = 16; o; o >>= 1) p += __shfl_xor_sync(0xffffffffu, p, o);
        if (lane == 0) g_sc[b * Ss + s] = p + bV[0];
    }
}

// ---------------- K3: softmax + context halves + token concat ----------------
__global__ __launch_bounds__(256) void attn_ctx(
    const float* __restrict__ enc, const float* __restrict__ tokens, int t) {
    const int b = blockIdx.x, y = blockIdx.y;
    const int tid = threadIdx.x, warp = tid >> 5, lane = tid & 31;
    __shared__ float at[Ss];

    if (warp == 0) {   // softmax over S=64 (redundant per half-block, cheap)
        float s0 = g_sc[b * Ss + lane], s1 = g_sc[b * Ss + 32 + lane];
        float mx = fmaxf(s0, s1);
#pragma unroll
        for (int o = 16; o; o >>= 1) mx = fmaxf(mx, __shfl_xor_sync(0xffffffffu, mx, o));
        float e0 = expf(s0 - mx), e1 = expf(s1 - mx);
        float sm = e0 + e1;
#pragma unroll
        for (int o = 16; o; o >>= 1) sm += __shfl_xor_sync(0xffffffffu, sm, o);
        float inv = 1.f / sm;
        at[lane] = e0 * inv;
        at[lane + 32] = e1 * inv;
    }
    __syncthreads();

    const float* eb = enc + (size_t)b * Ss * Hh + y * 256;
    float c = 0.f;
#pragma unroll 8
    for (int s = 0; s < Ss; s++) c += at[s] * eb[s * Hh + tid];
    float* x0 = g_x0 + b * (Hh + Ee);
    x0[y * 256 + tid] = c;
    if (y == 1) x0[Hh + tid] = tokens[((size_t)b * Tt + t) * Ee + tid];
}

// ---------------- LSTM matmul: split-K, repacked weights (R7-proven) ---------
template<int LAYER>
__global__ __launch_bounds__(256) void lstm_mm(int rp) {
    constexpr int KX  = LAYER ? Hh : (Hh + Ee);   // 512 or 768
    constexpr int CH  = (KX + Hh) / 8;            // 128 or 160
    constexpr int C2  = CH / 2;
    constexpr int STR = CH + 2;
    const float* X     = LAYER ? g_h0[1 - rp] : g_x0;
    const float* Hprev = LAYER ? g_h1[rp]     : g_h0[rp];
    const ull* wpk     = LAYER ? g_wpk1       : g_wpk0;

    __shared__ __align__(16) ull xd[32 * STR];

    const int tid = threadIdx.x;
    const int ksb = blockIdx.y;
    const int k0  = ksb * CH;
    const int bx  = blockIdx.x;
    const int c0  = bx * 32;

    {
        int m = tid >> 3;
        int part = tid & 7;
        constexpr int PER = CH / 8;
        int kb = part * PER;
        const float* xrow = X + (size_t)m * KX;
        const float* hrow = Hprev + m * Hh;
        ull* dst = xd + m * STR + kb;
#pragma unroll
        for (int q = 0; q < PER; q += 4) {
            int kg = k0 + kb + q;
            float4 v = (kg < KX) ? *(const float4*)(xrow + kg)
                                 : *(const float4*)(hrow + (kg - KX));
            dst[q + 0] = pack2(v.x, v.x);
            dst[q + 1] = pack2(v.y, v.y);
            dst[q + 2] = pack2(v.z, v.z);
            dst[q + 3] = pack2(v.w, v.w);
        }
    }
    __syncthreads();

    const int np = tid & 15;
    const int ms = tid >> 4;

    const ulonglong2* wp = (const ulonglong2*)(wpk + (size_t)(bx * 8 + ksb) * (CH * 16)) + np;
    const ulonglong2* xap = (const ulonglong2*)(xd + ms * STR);
    const ulonglong2* xbp = (const ulonglong2*)(xd + (ms + 16) * STR);

    ull acc0 = 0ull, acc1 = 0ull;
#pragma unroll 8
    for (int k2 = 0; k2 < C2; k2++) {
        ulonglong2 w = wp[k2 * 16];
        ulonglong2 a = xap[k2];
        ulonglong2 b = xbp[k2];
        ffma2(acc0, a.x, w.x);
        ffma2(acc1, b.x, w.x);
        ffma2(acc0, a.y, w.y);
        ffma2(acc1, b.y, w.y);
    }

    *(ull*)&g_zpart[((ksb * 32 + ms) * 2048) + c0 + 2 * np]      = acc0;
    *(ull*)&g_zpart[((ksb * 32 + ms + 16) * 2048) + c0 + 2 * np] = acc1;
}

// ---------------- gate epilogue (layer 0 every step; layer 1 only final) -----
// Generic over grid: idx = blockIdx*blockDim + tid covers Bb*Hh.
__global__ void lstm_gates(int layer, int rp, int t,
        const float* __restrict__ bias) {
    float *C, *Hout;
    if (layer == 0) { C = g_c0; Hout = g_h0[1 - rp]; }
    else            { C = g_c1; Hout = g_h1[1 - rp]; }
    int idx = blockIdx.x * blockDim.x + threadIdx.x;
    int m = idx >> 9, j = idx & 511;
    float zi = bias[j], zf = bias[Hh + j];
    float zg = bias[2 * Hh + j], zo = bias[3 * Hh + j];
#pragma unroll
    for (int ksb = 0; ksb < 8; ksb++) {
        const float* zr = g_zpart + (ksb * 32 + m) * 2048;
        zi += zr[j];
        zf += zr[Hh + j];
        zg += zr[2 * Hh + j];
        zo += zr[3 * Hh + j];
    }
    float ig = 1.f / (1.f + expf(-zi));
    float fg = 1.f / (1.f + expf(-zf));
    float og = 1.f / (1.f + expf(-zo));
    float cn = fg * C[idx] + ig * tanhf(zg);
    float hn = og * tanhf(cn);
    C[idx] = cn;
    Hout[idx] = hn;
    if (layer == 1) {
        __nv_bfloat16 hi = __float2bfloat16(hn);
        size_t hrow = (size_t)t * Bb * Hh + idx;
        g_HallHi[hrow] = hi;
        g_HallLo[hrow] = __float2bfloat16(hn - __bfloat162float(hi));
    }
}

// ---------------- logits: mma.sync bf16 split GEMM (R12-proven) ----------
#define LROW 80
#define LOPSZ (128 * LROW)
#define LBUF  (4 * LOPSZ)

__global__ __launch_bounds__(256, 1) void logits_tc(const float* __restrict__ bd,
                                                    float* __restrict__ out) {
    extern __shared__ __align__(16) char lsm[];
    const int tid = threadIdx.x;
    const int wid = tid >> 5, lane = tid & 31;
    const int colbase = blockIdx.x * 128;
    const int rowbase = blockIdx.y * 128;
    const int wm = wid >> 2, wn = wid & 3;

    const unsigned smbase = smem_u32(lsm);

    const int sr = tid >> 1, part = tid & 1;
    const uint4* gAH = (const uint4*)(g_HallHi + (size_t)(rowbase + sr) * Hh) + part * 2;
    const uint4* gAL = (const uint4*)(g_HallLo + (size_t)(rowbase + sr) * Hh) + part * 2;
    const uint4* gBH = (const uint4*)(g_WdtHi + (size_t)(colbase + sr) * Hh) + part * 2;
    const uint4* gBL = (const uint4*)(g_WdtLo + (size_t)(colbase + sr) * Hh) + part * 2;
    const unsigned sdst = sr * LROW + part * 32;

    float d[4][4][4];
#pragma unroll
    for (int mi = 0; mi < 4; mi++)
#pragma unroll
        for (int ni = 0; ni < 4; ni++)
#pragma unroll
            for (int q = 0; q < 4; q++) d[mi][ni][q] = 0.f;

    const unsigned aoff = (lane & 15) * LROW + (lane >> 4) * 16;
    const unsigned boff = ((lane & 7) + ((lane >> 4) << 3)) * LROW
                        + (((lane >> 3) & 1) << 4);

    uint4 rAH0 = gAH[0], rAH1 = gAH[1];
    uint4 rAL0 = gAL[0], rAL1 = gAL[1];
    uint4 rBH0 = gBH[0], rBH1 = gBH[1];
    uint4 rBL0 = gBL[0], rBL1 = gBL[1];
    {
        char* bb = lsm + sdst;
        *(uint4*)(bb + 0 * LOPSZ)      = rAH0; *(uint4*)(bb + 0 * LOPSZ + 16) = rAH1;
        *(uint4*)(bb + 1 * LOPSZ)      = rAL0; *(uint4*)(bb + 1 * LOPSZ + 16) = rAL1;
        *(uint4*)(bb + 2 * LOPSZ)      = rBH0; *(uint4*)(bb + 2 * LOPSZ + 16) = rBH1;
        *(uint4*)(bb + 3 * LOPSZ)      = rBL0; *(uint4*)(bb + 3 * LOPSZ + 16) = rBL1;
    }
    __syncthreads();

    for (int c = 0; c < 16; c++) {
        const int p = c & 1;
        if (c < 15) {
            int o = (c + 1) * 4;
            rAH0 = gAH[o]; rAH1 = gAH[o + 1];
            rAL0 = gAL[o]; rAL1 = gAL[o + 1];
            rBH0 = gBH[o]; rBH1 = gBH[o + 1];
            rBL0 = gBL[o]; rBL1 = gBL[o + 1];
        }

        const unsigned bAH = smbase + p * LBUF + 0 * LOPSZ;
        const unsigned bAL = smbase + p * LBUF + 1 * LOPSZ;
        const unsigned bBH = smbase + p * LBUF + 2 * LOPSZ;
        const unsigned bBL = smbase + p * LBUF + 3 * LOPSZ;

#pragma unroll
        for (int ks = 0; ks < 2; ks++) {
            unsigned aHi[4][4], aLo[4][4], bHi[4][2], bLo[4][2];
#pragma unroll
            for (int mi = 0; mi < 4; mi++) {
                unsigned r = (wm * 64 + mi * 16) * LROW + ks * 32;
                ldsm4(aHi[mi], bAH + r + aoff);
                ldsm4(aLo[mi], bAL + r + aoff);
            }
#pragma unroll
            for (int nh = 0; nh < 2; nh++) {
                unsigned r = (wn * 32 + nh * 16) * LROW + ks * 32;
                unsigned t4[4];
                ldsm4(t4, bBH + r + boff);
                bHi[nh * 2][0] = t4[0]; bHi[nh * 2][1] = t4[1];
                bHi[nh * 2 + 1][0] = t4[2]; bHi[nh * 2 + 1][1] = t4[3];
                ldsm4(t4, bBL + r + boff);
                bLo[nh * 2][0] = t4[0]; bLo[nh * 2][1] = t4[1];
                bLo[nh * 2 + 1][0] = t4[2]; bLo[nh * 2 + 1][1] = t4[3];
            }
#pragma unroll
            for (int mi = 0; mi < 4; mi++)
#pragma unroll
                for (int ni = 0; ni < 4; ni++) {
                    mma16816(d[mi][ni], aHi[mi], bHi[ni]);
                    mma16816(d[mi][ni], aHi[mi], bLo[ni]);
                    mma16816(d[mi][ni], aLo[mi], bHi[ni]);
                }
        }

        if (c < 15) {
            char* bb = lsm + ((c + 1) & 1) * LBUF + sdst;
            *(uint4*)(bb + 0 * LOPSZ)      = rAH0; *(uint4*)(bb + 0 * LOPSZ + 16) = rAH1;
            *(uint4*)(bb + 1 * LOPSZ)      = rAL0; *(uint4*)(bb + 1 * LOPSZ + 16) = rAL1;
            *(uint4*)(bb + 2 * LOPSZ)      = rBH0; *(uint4*)(bb + 2 * LOPSZ + 16) = rBH1;
            *(uint4*)(bb + 3 * LOPSZ)      = rBL0; *(uint4*)(bb + 3 * LOPSZ + 16) = rBL1;
            __syncthreads();
        }
    }

    const int g = lane >> 2, tg = lane & 3;
#pragma unroll
    for (int mi = 0; mi < 4; mi++) {
#pragma unroll
        for (int half = 0; half < 2; half++) {
            int r = rowbase + wm * 64 + mi * 16 + g + half * 8;
            int orow = (r & 31) * Tt + (r >> 5);
            float* op = out + (size_t)orow * DVv;
#pragma unroll
            for (int ni = 0; ni < 4; ni++) {
                int col = colbase + wn * 32 + ni * 8 + tg * 2;
                float2 bj = *(const float2*)(bd + col);
                float2 v;
                v.x = d[mi][ni][half * 2 + 0] + bj.x;
                v.y = d[mi][ni][half * 2 + 1] + bj.y;
                *(float2*)(op + col) = v;
            }
        }
    }
}

// ---------------- launch ----------------
extern "C" void kernel_launch(void* const* d_in, const int* in_sizes, int n_in,
                              void* d_out, int out_size) {
    const float* initial_input  = (const float*)d_in[0];
    const float* hidden0        = (const float*)d_in[1];
    const float* cell0          = (const float*)d_in[2];
    const float* encoder_output = (const float*)d_in[3];
    const float* W1 = (const float*)d_in[4];
    const float* b1 = (const float*)d_in[5];
    const float* W2 = (const float*)d_in[6];
    const float* b2 = (const float*)d_in[7];
    const float* V  = (const float*)d_in[8];
    const float* bV = (const float*)d_in[9];
    const float* Wx0 = (const float*)d_in[10];
    const float* Wh0 = (const float*)d_in[11];
    const float* bL0 = (const float*)d_in[12];
    const float* Wx1 = (const float*)d_in[13];
    const float* Wh1 = (const float*)d_in[14];
    const float* bL1 = (const float*)d_in[15];
    const float* Wd  = (const float*)d_in[16];
    const float* bd  = (const float*)d_in[17];
    float* out = (float*)d_out;

    cudaFuncSetAttribute(logits_tc, cudaFuncAttributeMaxDynamicSharedMemorySize,
                         2 * LBUF);

    init_state<<<(Bb * Hh + 255) / 256, 256>>>(hidden0, cell0);

    repack_w<0><<<(64 * 8 * 160 * 16) / 256, 256>>>(Wx0, Wh0);
    repack_w<1><<<(64 * 8 * 128 * 16) / 256, 256>>>(Wx1, Wh1);

    sgemm_enc<<<dim3(Aa / 64, (Bb * Ss) / 64), 256>>>(encoder_output, W2, b2);

    for (int t = 0; t < Tt; t++) {
        int rp = t & 1;
        gates_q<<<4 * Bb, 256>>>(W1, bL1, rp, t, t > 0);
        attn_scores<<<dim3(Bb, 4), 256>>>(b1, V, bV);
        attn_ctx<<<dim3(Bb, 2), 256>>>(encoder_output, initial_input, t);
        lstm_mm<0><<<dim3(64, 8), 256>>>(rp);
        lstm_gates<<<128, 128>>>(0, rp, t, bL0);
        lstm_mm<1><<<dim3(64, 8), 256>>>(rp);
    }
    // final layer-1 gates (t = 63)
    lstm_gates<<<128, 128>>>(1, (Tt - 1) & 1, Tt - 1, bL1);

    // Wd transpose only feeds logits; placed here so early ncu capture slots
    // land on recurrence kernels instead.
    transpose_wd<<<dim3(DVv / 32, Hh / 32), 256>>>(Wd);

    logits_tc<<<dim3(DVv / 128, (Tt * Bb) / 128), 256, 2 * LBUF>>>(bd, out);

    long long total = (long long)Bb * Tt * DVv;
    if ((long long)out_size >= total + 4LL * Bb * Hh)
        write_tail<<<(Bb * Hh + 255) / 256, 256>>>(out + total);
}